// round 8
// baseline (speedup 1.0000x reference)
#include <cuda_runtime.h>
#include <cuda_bf16.h>
#include <math.h>
#include <stdint.h>

#define BB 4096
#define DD 256
#define TT 64

// ================= PTX helpers (baseline ISA only) =================
__device__ __forceinline__ uint32_t smem_u32(const void* p) {
    uint32_t a;
    asm("{ .reg .u64 t; cvta.to.shared.u64 t, %1; cvt.u32.u64 %0, t; }" : "=r"(a) : "l"(p));
    return a;
}
__device__ __forceinline__ void cp16(uint32_t saddr, const void* g) {
    asm volatile("cp.async.cg.shared.global [%0], [%1], 16;" :: "r"(saddr), "l"(g));
}
__device__ __forceinline__ void ldsm4(uint32_t* r, uint32_t addr) {
    asm volatile("ldmatrix.sync.aligned.m8n8.x4.shared.b16 {%0,%1,%2,%3}, [%4];"
        : "=r"(r[0]), "=r"(r[1]), "=r"(r[2]), "=r"(r[3]) : "r"(addr));
}
__device__ __forceinline__ void mma16816(float* c, const uint32_t* a, uint32_t b0, uint32_t b1) {
    asm volatile("mma.sync.aligned.m16n8k16.row.col.f32.bf16.bf16.f32 "
        "{%0,%1,%2,%3}, {%4,%5,%6,%7}, {%8,%9}, {%0,%1,%2,%3};"
        : "+f"(c[0]), "+f"(c[1]), "+f"(c[2]), "+f"(c[3])
        : "r"(a[0]), "r"(a[1]), "r"(a[2]), "r"(a[3]), "r"(b0), "r"(b1));
}

// ================= scratch pool =================
static constexpr size_t SZ_XG  = (size_t)BB * 768 * 2;
static constexpr size_t SZ_XS  = (size_t)BB * 512 * 2;
static constexpr size_t SZ_BD  = (size_t)BB * 256 * 2;
static constexpr size_t SZ_Q0  = (size_t)2 * BB * 256 * 2;
static constexpr size_t SZ_BDF = (size_t)BB * 256 * 4;

static constexpr size_t O_XG_H  = 0;
static constexpr size_t O_XG_L  = O_XG_H  + SZ_XG;
static constexpr size_t O_XE_H  = O_XG_L  + SZ_XG;
static constexpr size_t O_XE_L  = O_XE_H  + SZ_XG;
static constexpr size_t O_XQS_H = O_XE_L  + SZ_XG;
static constexpr size_t O_XQS_L = O_XQS_H + SZ_XS;
static constexpr size_t O_XRS_H = O_XQS_L + SZ_XS;
static constexpr size_t O_XRS_L = O_XRS_H + SZ_XS;
static constexpr size_t O_XPL_H = O_XRS_L + SZ_XS;
static constexpr size_t O_XPL_L = O_XPL_H + SZ_XS;
static constexpr size_t O_Q0_H  = O_XPL_L + SZ_XS;
static constexpr size_t O_Q0_L  = O_Q0_H  + SZ_Q0;
static constexpr size_t O_GH_H  = O_Q0_L  + SZ_Q0;
static constexpr size_t O_GH_L  = O_GH_H  + SZ_BD;
static constexpr size_t O_E0_H  = O_GH_L  + SZ_BD;
static constexpr size_t O_E0_L  = O_E0_H  + SZ_BD;
static constexpr size_t O_QS_H  = O_E0_L  + SZ_BD;
static constexpr size_t O_QS_L  = O_QS_H  + SZ_BD;
static constexpr size_t O_RS_H  = O_QS_L  + SZ_BD;
static constexpr size_t O_RS_L  = O_RS_H  + SZ_BD;
static constexpr size_t O_QSF   = O_RS_L  + SZ_BD;
static constexpr size_t O_RSF   = O_QSF   + SZ_BDF;
static constexpr size_t SZ_W768 = (size_t)768 * 768 * 2;
static constexpr size_t SZ_W512 = (size_t)768 * 512 * 2;
static constexpr size_t SZ_W256 = (size_t)768 * 256 * 2;
static constexpr size_t O_WGIH_H = O_RSF + SZ_BDF;
static constexpr size_t O_WGIH_L = O_WGIH_H + SZ_W768;
static constexpr size_t O_WGHH_H = O_WGIH_L + SZ_W768;
static constexpr size_t O_WGHH_L = O_WGHH_H + SZ_W256;
static constexpr size_t O_WPIH_H = O_WGHH_L + SZ_W256;
static constexpr size_t O_WPIH_L = O_WPIH_H + SZ_W512;
static constexpr size_t O_WPHH_H = O_WPIH_L + SZ_W512;
static constexpr size_t O_WPHH_L = O_WPHH_H + SZ_W256;
static constexpr size_t O_WLIH_H = O_WPHH_L + SZ_W256;
static constexpr size_t O_WLIH_L = O_WLIH_H + SZ_W512;
static constexpr size_t O_WLHH_H = O_WLIH_L + SZ_W512;
static constexpr size_t O_WLHH_L = O_WLHH_H + SZ_W256;
static constexpr size_t O_WRIH_H = O_WLHH_L + SZ_W256;
static constexpr size_t O_WRIH_L = O_WRIH_H + SZ_W512;
static constexpr size_t O_WRHH_H = O_WRIH_L + SZ_W512;
static constexpr size_t O_WRHH_L = O_WRHH_H + SZ_W256;
static constexpr size_t O_WEIH_H = O_WRHH_L + SZ_W256;
static constexpr size_t O_WEIH_L = O_WEIH_H + SZ_W768;
static constexpr size_t O_WEHH_H = O_WEIH_L + SZ_W768;
static constexpr size_t O_WEHH_L = O_WEHH_H + SZ_W256;
static constexpr size_t O_SELROW = O_WEHH_L + SZ_W256;
static constexpr size_t O_QMIDX  = O_SELROW + BB * 4;
static constexpr size_t POOL_SZ  = O_QMIDX + BB * 4;

__device__ __align__(1024) unsigned char g_pool[POOL_SZ];

// ================= helpers =================
__device__ __forceinline__ void bsplit(float x, __nv_bfloat16* hp, __nv_bfloat16* lp, size_t i) {
    __nv_bfloat16 h = __float2bfloat16(x);
    hp[i] = h;
    lp[i] = __float2bfloat16(x - __bfloat162float(h));
}

// ================= conv_all =================
struct ConvSeg { const float* src; __nv_bfloat16* hi; __nv_bfloat16* lo; int nblk; };
struct ConvTable { ConvSeg s[13]; };

__global__ void conv_all_kernel(ConvTable t) {
    int blk = blockIdx.x;
    #pragma unroll 1
    for (int i = 0; i < 13; i++) {
        int nb = t.s[i].nblk;
        if (blk < nb) {
            int idx = blk * 256 + threadIdx.x;
            bsplit(t.s[i].src[idx], t.s[i].hi, t.s[i].lo, idx);
            return;
        }
        blk -= nb;
    }
}

// ================= prep =================
__global__ void prep_kernel(const float* __restrict__ U, const float* __restrict__ qmask,
                            const float* __restrict__ q0, const float* __restrict__ r0,
                            float* __restrict__ qsf, float* __restrict__ rsf,
                            __nv_bfloat16* qsh, __nv_bfloat16* qsl,
                            __nv_bfloat16* rsh, __nv_bfloat16* rsl,
                            __nv_bfloat16* xgh, __nv_bfloat16* xgl,
                            __nv_bfloat16* xqsh, __nv_bfloat16* xqsl,
                            __nv_bfloat16* xrsh, __nv_bfloat16* xrsl,
                            __nv_bfloat16* xplh, __nv_bfloat16* xpll,
                            __nv_bfloat16* xeh,  __nv_bfloat16* xel,
                            int* __restrict__ selrow, int* __restrict__ qmidx) {
    int i = blockIdx.x * 256 + threadIdx.x;
    int b = i >> 8, d = i & 255;
    int qm = (qmask[b * 2 + 1] > qmask[b * 2]) ? 1 : 0;
    if (d == 0) { qmidx[b] = qm; selrow[b] = b * 2 + qm; }
    float q = q0[(size_t)(b * 2 + qm) * DD + d];
    float r = r0[(size_t)(b * 2 + qm) * DD + d];
    float u = U[i];
    qsf[i] = q; rsf[i] = r;
    bsplit(q, qsh, qsl, i);
    bsplit(r, rsh, rsl, i);
    size_t o = (size_t)b * 768 + d;
    bsplit(q, xgh, xgl, o);
    bsplit(r, xgh, xgl, o + 256);
    bsplit(u, xgh, xgl, o + 512);
    size_t o2 = (size_t)b * 512 + 256 + d;
    bsplit(u, xqsh, xqsl, o2);
    bsplit(u, xrsh, xrsl, o2);
    bsplit(u, xplh, xpll, o2);
    bsplit(u, xeh, xel, o);
}

// ================= attention =================
__global__ void att_kernel(const float* __restrict__ gh, const float* __restrict__ attw,
                           __nv_bfloat16* __restrict__ xrsh, __nv_bfloat16* __restrict__ xrsl,
                           float* __restrict__ alpha_out) {
    extern __shared__ float sh[];
    __shared__ float s_aw[DD];
    __shared__ float s_scale[TT];
    __shared__ float s_alpha[TT];
    int b = blockIdx.x, tid = threadIdx.x;
    s_aw[tid] = attw[tid];
    for (int t = 0; t < TT; t++)
        sh[t * DD + tid] = gh[((size_t)t * BB + b) * DD + tid];
    __syncthreads();
    int w = tid >> 5, lane = tid & 31;
    for (int t = w; t < TT; t += 8) {
        float s = 0.f;
        #pragma unroll
        for (int i = 0; i < 8; i++) s += sh[t * DD + lane + i * 32] * s_aw[lane + i * 32];
        #pragma unroll
        for (int o = 16; o > 0; o >>= 1) s += __shfl_down_sync(0xffffffffu, s, o);
        if (lane == 0) s_scale[t] = s;
    }
    __syncthreads();
    if (w == 0) {
        float v0 = s_scale[lane], v1 = s_scale[lane + 32];
        float m = fmaxf(v0, v1);
        #pragma unroll
        for (int o = 16; o > 0; o >>= 1) m = fmaxf(m, __shfl_xor_sync(0xffffffffu, m, o));
        float e0 = expf(v0 - m), e1 = expf(v1 - m);
        float s = e0 + e1;
        #pragma unroll
        for (int o = 16; o > 0; o >>= 1) s += __shfl_xor_sync(0xffffffffu, s, o);
        float inv = 1.f / s;
        s_alpha[lane] = e0 * inv;
        s_alpha[lane + 32] = e1 * inv;
        alpha_out[(size_t)b * TT + lane] = e0 * inv;
        alpha_out[(size_t)b * TT + lane + 32] = e1 * inv;
    }
    __syncthreads();
    float acc = 0.f;
    for (int t = 0; t < TT; t++) acc += s_alpha[t] * sh[t * DD + tid];
    bsplit(acc, xrsh, xrsl, (size_t)b * 512 + tid);
}

// ================= fused GRU via mma.sync — hoisted-address version =================
#define TILE_SB 5120
#define STAGE_SB (8 * TILE_SB)
#define GRU_SMEM (2 * STAGE_SB)

__global__ __launch_bounds__(256, 2) void gru_mma_kernel(
    const __nv_bfloat16* __restrict__ Xhi, const __nv_bfloat16* __restrict__ Xlo,
    int K, int xshift,
    const __nv_bfloat16* __restrict__ Hhi, const __nv_bfloat16* __restrict__ Hlo,
    const float* __restrict__ Hf,
    const __nv_bfloat16* __restrict__ Wih_hi, const __nv_bfloat16* __restrict__ Wih_lo,
    const __nv_bfloat16* __restrict__ Whh_hi, const __nv_bfloat16* __restrict__ Whh_lo,
    const float* __restrict__ bih, const float* __restrict__ bhh,
    float* __restrict__ Out, const int* __restrict__ out_rows,
    const int* __restrict__ selrow, int zero_other,
    __nv_bfloat16* __restrict__ x1h, __nv_bfloat16* __restrict__ x1l,
    int x1_stride, int x1_off, int x1_sel,
    __nv_bfloat16* __restrict__ x2h, __nv_bfloat16* __restrict__ x2l,
    int x2_stride, int x2_off)
{
    extern __shared__ __align__(16) char dsm[];
    const uint32_t smb = smem_u32(dsm);

    const int tid = threadIdx.x;
    const int wid = tid >> 5, lane = tid & 31;
    const int warp_m = wid & 3, warp_n = wid >> 2;
    const int row0 = blockIdx.x * 64, c0 = blockIdx.y * 64;

    const int lr = tid >> 2;
    const int lc = (tid & 3) * 8;
    const uint32_t st0 = smb + (uint32_t)lr * 80 + (tid & 3) * 16;

    const int nch0 = K / 32;
    const int ntot = nch0 + 8;

    float acc[4][16];
    #pragma unroll
    for (int g = 0; g < 4; g++)
        #pragma unroll
        for (int d = 0; d < 16; d++) acc[g][d] = 0.f;

    // ldsm lane base addresses (smem, stage 0)
    const uint32_t aoffr = smb
        + ((uint32_t)(warp_m * 16 + (lane & 7) + ((lane >> 3) & 1) * 8)) * 80
        + (uint32_t)(lane >> 4) * 16;
    const uint32_t boffr = smb
        + ((uint32_t)(warp_n * 32 + (lane & 7) + (lane >> 4) * 8)) * 80
        + (uint32_t)((lane >> 3) & 1) * 16;

    // ---- hoisted global pointers (phase 0) ----
    const __nv_bfloat16* pa  = Xhi + (size_t)((row0 + lr) >> xshift) * K + lc;
    const __nv_bfloat16* pal = Xlo + (size_t)((row0 + lr) >> xshift) * K + lc;
    const __nv_bfloat16* pwh = Wih_hi + (size_t)(c0 + lr) * K + lc;
    const __nv_bfloat16* pwl = Wih_lo + (size_t)(c0 + lr) * K + lc;
    size_t goff = (size_t)256 * K;          // elements between gate blocks

    uint32_t pref_stg = 0;
    uint32_t cons_stg = 0;

    auto do_prefetch = [&]() {
        uint32_t s = st0 + pref_stg;
        cp16(s + 0 * TILE_SB, pa);
        cp16(s + 1 * TILE_SB, pal);
        cp16(s + 2 * TILE_SB, pwh);
        cp16(s + 3 * TILE_SB, pwl);
        cp16(s + 4 * TILE_SB, pwh + goff);
        cp16(s + 5 * TILE_SB, pwl + goff);
        cp16(s + 6 * TILE_SB, pwh + 2 * goff);
        cp16(s + 7 * TILE_SB, pwl + 2 * goff);
        pa += 32; pal += 32; pwh += 32; pwl += 32;
        pref_stg ^= STAGE_SB;
    };
    auto set_phase1 = [&]() {
        pa  = Hhi + (size_t)(row0 + lr) * 256 + lc;
        pal = Hlo + (size_t)(row0 + lr) * 256 + lc;
        pwh = Whh_hi + (size_t)(c0 + lr) * 256 + lc;
        pwl = Whh_lo + (size_t)(c0 + lr) * 256 + lc;
        goff = (size_t)256 * 256;
    };

    do_prefetch();
    asm volatile("cp.async.commit_group;");

    #pragma unroll 1
    for (int i = 0; i < ntot; i++) {
        if (i + 1 < ntot) {
            if (i + 1 == nch0) set_phase1();
            do_prefetch();
        }
        asm volatile("cp.async.commit_group;");
        asm volatile("cp.async.wait_group 1;");
        __syncthreads();

        const int ph = (i >= nch0);
        const uint32_t A0 = aoffr + cons_stg;
        const uint32_t B0 = boffr + cons_stg;

        #pragma unroll
        for (int s = 0; s < 2; s++) {
            const uint32_t ka = (uint32_t)s * 32;
            uint32_t ah[4], al[4];
            ldsm4(ah, A0 + ka);
            ldsm4(al, A0 + TILE_SB + ka);
            #pragma unroll
            for (int g = 0; g < 3; g++) {
                const int ag = (ph && g == 2) ? 3 : g;
                #pragma unroll
                for (int pair = 0; pair < 2; pair++) {
                    uint32_t bh[4], bl[4];
                    uint32_t ba = B0 + (2 + g * 2) * TILE_SB + pair * 1280 + ka;
                    ldsm4(bh, ba);
                    ldsm4(bl, ba + TILE_SB);
                    float* A0p = acc[ag] + pair * 8;
                    mma16816(A0p,     ah, bh[0], bh[1]);
                    mma16816(A0p + 4, ah, bh[2], bh[3]);
                    mma16816(A0p,     ah, bl[0], bl[1]);
                    mma16816(A0p + 4, ah, bl[2], bl[3]);
                    mma16816(A0p,     al, bh[0], bh[1]);
                    mma16816(A0p + 4, al, bh[2], bh[3]);
                }
            }
        }
        cons_stg ^= STAGE_SB;
        __syncthreads();
    }

    // ---- epilogue ----
    const int mrow = row0 + warp_m * 16 + (lane >> 2);
    const int colbase = c0 + warp_n * 32 + (lane & 3) * 2;
    #pragma unroll
    for (int half = 0; half < 2; half++) {
        int m = mrow + half * 8;
        int orow = out_rows ? out_rows[m] : m;
        const float* hrow = Hf + (size_t)m * 256;
        float* op = Out + (size_t)orow * 256;
        float* oo = zero_other ? (Out + (size_t)(orow ^ 1) * 256) : nullptr;
        int x1b = x1_sel ? (m >> 1) : m;
        bool x1ok = x1h && (!x1_sel || (selrow[x1b] == m));
        #pragma unroll
        for (int nt = 0; nt < 4; nt++) {
            #pragma unroll
            for (int e = 0; e < 2; e++) {
                int col = colbase + nt * 8 + e;
                int d = nt * 4 + half * 2 + e;
                float ar = acc[0][d] + bih[col] + bhh[col];
                float az = acc[1][d] + bih[256 + col] + bhh[256 + col];
                float r = 1.f / (1.f + expf(-ar));
                float z = 1.f / (1.f + expf(-az));
                float n = tanhf(acc[2][d] + bih[512 + col] + r * (acc[3][d] + bhh[512 + col]));
                float v = (1.f - z) * n + z * hrow[col];
                op[col] = v;
                if (oo) oo[col] = 0.f;
                if (x1ok) bsplit(v, x1h, x1l, (size_t)x1b * x1_stride + x1_off + col);
                if (x2h)  bsplit(v, x2h, x2l, (size_t)m * x2_stride + x2_off + col);
            }
        }
    }
}

// ================= launch =================
extern "C" void kernel_launch(void* const* d_in, const int* in_sizes, int n_in,
                              void* d_out, int out_size) {
    const float* U      = (const float*)d_in[0];
    const float* qmask  = (const float*)d_in[1];
    const float* g_hist = (const float*)d_in[2];
    const float* q0     = (const float*)d_in[3];
    const float* r0     = (const float*)d_in[4];
    const float* e0     = (const float*)d_in[5];
    const float* g_wih  = (const float*)d_in[6];
    const float* g_whh  = (const float*)d_in[7];
    const float* g_bih  = (const float*)d_in[8];
    const float* g_bhh  = (const float*)d_in[9];
    const float* p_wih  = (const float*)d_in[10];
    const float* p_whh  = (const float*)d_in[11];
    const float* p_bih  = (const float*)d_in[12];
    const float* p_bhh  = (const float*)d_in[13];
    const float* pl_wih = (const float*)d_in[14];
    const float* pl_whh = (const float*)d_in[15];
    const float* pl_bih = (const float*)d_in[16];
    const float* pl_bhh = (const float*)d_in[17];
    const float* r_wih  = (const float*)d_in[18];
    const float* r_whh  = (const float*)d_in[19];
    const float* r_bih  = (const float*)d_in[20];
    const float* r_bhh  = (const float*)d_in[21];
    const float* e_wih  = (const float*)d_in[22];
    const float* e_whh  = (const float*)d_in[23];
    const float* e_bih  = (const float*)d_in[24];
    const float* e_bhh  = (const float*)d_in[25];
    const float* att_w  = (const float*)d_in[26];

    float* out = (float*)d_out;
    float* o_g = out;
    float* o_q = out + 1048576;
    float* o_r = out + 3145728;
    float* o_e = out + 5242880;
    float* o_a = out + 6291456;

    void* poolv;
    cudaGetSymbolAddress(&poolv, g_pool);
    char* pool = (char*)poolv;
    #define BF(off) ((__nv_bfloat16*)(pool + (off)))
    #define FP(off) ((float*)(pool + (off)))
    int* selrow = (int*)(pool + O_SELROW);
    int* qmidx  = (int*)(pool + O_QMIDX);

    // side stream + events: created on the first (non-captured) correctness call
    static cudaStream_t s2 = nullptr;
    static cudaEvent_t evA = nullptr, evB = nullptr;
    if (s2 == nullptr) {
        cudaStreamCreate(&s2);
        cudaEventCreateWithFlags(&evA, cudaEventDisableTiming);
        cudaEventCreateWithFlags(&evB, cudaEventDisableTiming);
        cudaFuncSetAttribute(att_kernel, cudaFuncAttributeMaxDynamicSharedMemorySize,
                             TT * DD * (int)sizeof(float));
        cudaFuncSetAttribute(gru_mma_kernel, cudaFuncAttributeMaxDynamicSharedMemorySize, GRU_SMEM);
    }

    const float* ghl = g_hist + (size_t)63 * BB * DD;

    // 1) conversions (main stream)
    ConvTable ct;
    int ti = 0, total_blk = 0;
    auto addseg = [&](const float* s, size_t oh, size_t ol, int n) {
        ct.s[ti].src = s; ct.s[ti].hi = BF(oh); ct.s[ti].lo = BF(ol);
        ct.s[ti].nblk = n / 256; total_blk += n / 256; ti++;
    };
    addseg(g_wih,  O_WGIH_H, O_WGIH_L, 768 * 768);
    addseg(g_whh,  O_WGHH_H, O_WGHH_L, 768 * 256);
    addseg(p_wih,  O_WPIH_H, O_WPIH_L, 768 * 512);
    addseg(p_whh,  O_WPHH_H, O_WPHH_L, 768 * 256);
    addseg(pl_wih, O_WLIH_H, O_WLIH_L, 768 * 512);
    addseg(pl_whh, O_WLHH_H, O_WLHH_L, 768 * 256);
    addseg(r_wih,  O_WRIH_H, O_WRIH_L, 768 * 512);
    addseg(r_whh,  O_WRHH_H, O_WRHH_L, 768 * 256);
    addseg(e_wih,  O_WEIH_H, O_WEIH_L, 768 * 768);
    addseg(e_whh,  O_WEHH_H, O_WEHH_L, 768 * 256);
    addseg(q0,     O_Q0_H,   O_Q0_L,   2 * BB * 256);
    addseg(ghl,    O_GH_H,   O_GH_L,   BB * 256);
    addseg(e0,     O_E0_H,   O_E0_L,   BB * 256);
    conv_all_kernel<<<total_blk, 256>>>(ct);

    // 2) prep (main stream)
    prep_kernel<<<BB, 256>>>(U, qmask, q0, r0,
        FP(O_QSF), FP(O_RSF), BF(O_QS_H), BF(O_QS_L), BF(O_RS_H), BF(O_RS_L),
        BF(O_XG_H), BF(O_XG_L),
        BF(O_XQS_H), BF(O_XQS_L), BF(O_XRS_H), BF(O_XRS_L),
        BF(O_XPL_H), BF(O_XPL_L), BF(O_XE_H), BF(O_XE_L),
        selrow, qmidx);

    // fork: side stream runs att -> rs, concurrent with main GRU chain
    cudaEventRecord(evA, 0);
    cudaStreamWaitEvent(s2, evA, 0);

    // 3) attention (s2) -> xrs first half + alpha
    att_kernel<<<BB, 256, TT * DD * sizeof(float), s2>>>(g_hist, att_w,
        BF(O_XRS_H), BF(O_XRS_L), o_a);

    // rs GRU (s2): selected rows, scatter + zero sibling row
    gru_mma_kernel<<<dim3(BB / 64, 4), 256, GRU_SMEM, s2>>>(
        BF(O_XRS_H), BF(O_XRS_L), 512, 0,
        BF(O_RS_H), BF(O_RS_L), FP(O_RSF),
        BF(O_WRIH_H), BF(O_WRIH_L), BF(O_WRHH_H), BF(O_WRHH_L),
        r_bih, r_bhh, o_r, selrow,
        nullptr, 1,
        nullptr, nullptr, 0, 0, 0,
        nullptr, nullptr, 0, 0);
    cudaEventRecord(evB, s2);

    // 4) g GRU (main): K=768; epilogue writes xqs[0:256] and xe[512:768]
    gru_mma_kernel<<<dim3(BB / 64, 4), 256, GRU_SMEM>>>(
        BF(O_XG_H), BF(O_XG_L), 768, 0,
        BF(O_GH_H), BF(O_GH_L), ghl,
        BF(O_WGIH_H), BF(O_WGIH_L), BF(O_WGHH_H), BF(O_WGHH_L),
        g_bih, g_bhh, o_g, nullptr,
        nullptr, 0,
        BF(O_XQS_H), BF(O_XQS_L), 512, 0, 0,
        BF(O_XE_H), BF(O_XE_L), 768, 512);

    // 5) qs GRU (main): 8192 rows; epilogue writes xpl[0:256] for selected rows
    gru_mma_kernel<<<dim3(2 * BB / 64, 4), 256, GRU_SMEM>>>(
        BF(O_XQS_H), BF(O_XQS_L), 512, 1,
        BF(O_Q0_H), BF(O_Q0_L), q0,
        BF(O_WPIH_H), BF(O_WPIH_L), BF(O_WPHH_H), BF(O_WPHH_L),
        p_bih, p_bhh, o_q, nullptr,
        selrow, 0,
        BF(O_XPL_H), BF(O_XPL_L), 512, 0, 1,
        nullptr, nullptr, 0, 0);

    // 6) ql GRU (main): selected rows, scatter into q_; epilogue writes xe[256:512]
    gru_mma_kernel<<<dim3(BB / 64, 4), 256, GRU_SMEM>>>(
        BF(O_XPL_H), BF(O_XPL_L), 512, 0,
        BF(O_QS_H), BF(O_QS_L), FP(O_QSF),
        BF(O_WLIH_H), BF(O_WLIH_L), BF(O_WLHH_H), BF(O_WLHH_L),
        pl_bih, pl_bhh, o_q, selrow,
        nullptr, 0,
        BF(O_XE_H), BF(O_XE_L), 768, 256, 0,
        nullptr, nullptr, 0, 0);

    // 7) e GRU (main): K=768
    gru_mma_kernel<<<dim3(BB / 64, 4), 256, GRU_SMEM>>>(
        BF(O_XE_H), BF(O_XE_L), 768, 0,
        BF(O_E0_H), BF(O_E0_L), e0,
        BF(O_WEIH_H), BF(O_WEIH_L), BF(O_WEHH_H), BF(O_WEHH_L),
        e_bih, e_bhh, o_e, nullptr,
        nullptr, 0,
        nullptr, nullptr, 0, 0, 0,
        nullptr, nullptr, 0, 0);

    // join: main stream waits for rs branch
    cudaStreamWaitEvent(0, evB, 0);
    #undef BF
    #undef FP
}

// round 9
// speedup vs baseline: 1.6496x; 1.6496x over previous
#include <cuda_runtime.h>
#include <cuda_bf16.h>
#include <math.h>
#include <stdint.h>

#define BB 4096
#define DD 256
#define TT 64

// ================= PTX helpers (baseline ISA only) =================
__device__ __forceinline__ uint32_t smem_u32(const void* p) {
    uint32_t a;
    asm("{ .reg .u64 t; cvta.to.shared.u64 t, %1; cvt.u32.u64 %0, t; }" : "=r"(a) : "l"(p));
    return a;
}
__device__ __forceinline__ void cp16(uint32_t saddr, const void* g) {
    asm volatile("cp.async.cg.shared.global [%0], [%1], 16;" :: "r"(saddr), "l"(g));
}
__device__ __forceinline__ void ldsm4(uint32_t* r, uint32_t addr) {
    asm volatile("ldmatrix.sync.aligned.m8n8.x4.shared.b16 {%0,%1,%2,%3}, [%4];"
        : "=r"(r[0]), "=r"(r[1]), "=r"(r[2]), "=r"(r[3]) : "r"(addr));
}
__device__ __forceinline__ void mma16816(float* c, const uint32_t* a, uint32_t b0, uint32_t b1) {
    asm volatile("mma.sync.aligned.m16n8k16.row.col.f32.bf16.bf16.f32 "
        "{%0,%1,%2,%3}, {%4,%5,%6,%7}, {%8,%9}, {%0,%1,%2,%3};"
        : "+f"(c[0]), "+f"(c[1]), "+f"(c[2]), "+f"(c[3])
        : "r"(a[0]), "r"(a[1]), "r"(a[2]), "r"(a[3]), "r"(b0), "r"(b1));
}

// ================= scratch pool =================
static constexpr size_t SZ_XG  = (size_t)BB * 768 * 2;
static constexpr size_t SZ_XS  = (size_t)BB * 512 * 2;
static constexpr size_t SZ_BD  = (size_t)BB * 256 * 2;
static constexpr size_t SZ_Q0  = (size_t)2 * BB * 256 * 2;
static constexpr size_t SZ_BDF = (size_t)BB * 256 * 4;

static constexpr size_t O_XG_H  = 0;
static constexpr size_t O_XG_L  = O_XG_H  + SZ_XG;
static constexpr size_t O_XE_H  = O_XG_L  + SZ_XG;
static constexpr size_t O_XE_L  = O_XE_H  + SZ_XG;
static constexpr size_t O_XQS_H = O_XE_L  + SZ_XG;
static constexpr size_t O_XQS_L = O_XQS_H + SZ_XS;
static constexpr size_t O_XRS_H = O_XQS_L + SZ_XS;
static constexpr size_t O_XRS_L = O_XRS_H + SZ_XS;
static constexpr size_t O_XPL_H = O_XRS_L + SZ_XS;
static constexpr size_t O_XPL_L = O_XPL_H + SZ_XS;
static constexpr size_t O_Q0_H  = O_XPL_L + SZ_XS;
static constexpr size_t O_Q0_L  = O_Q0_H  + SZ_Q0;
static constexpr size_t O_GH_H  = O_Q0_L  + SZ_Q0;
static constexpr size_t O_GH_L  = O_GH_H  + SZ_BD;
static constexpr size_t O_E0_H  = O_GH_L  + SZ_BD;
static constexpr size_t O_E0_L  = O_E0_H  + SZ_BD;
static constexpr size_t O_QS_H  = O_E0_L  + SZ_BD;
static constexpr size_t O_QS_L  = O_QS_H  + SZ_BD;
static constexpr size_t O_RS_H  = O_QS_L  + SZ_BD;
static constexpr size_t O_RS_L  = O_RS_H  + SZ_BD;
static constexpr size_t O_QSF   = O_RS_L  + SZ_BD;
static constexpr size_t O_RSF   = O_QSF   + SZ_BDF;
static constexpr size_t SZ_W768 = (size_t)768 * 768 * 2;
static constexpr size_t SZ_W512 = (size_t)768 * 512 * 2;
static constexpr size_t SZ_W256 = (size_t)768 * 256 * 2;
static constexpr size_t O_WGIH_H = O_RSF + SZ_BDF;
static constexpr size_t O_WGIH_L = O_WGIH_H + SZ_W768;
static constexpr size_t O_WGHH_H = O_WGIH_L + SZ_W768;
static constexpr size_t O_WGHH_L = O_WGHH_H + SZ_W256;
static constexpr size_t O_WPIH_H = O_WGHH_L + SZ_W256;
static constexpr size_t O_WPIH_L = O_WPIH_H + SZ_W512;
static constexpr size_t O_WPHH_H = O_WPIH_L + SZ_W512;
static constexpr size_t O_WPHH_L = O_WPHH_H + SZ_W256;
static constexpr size_t O_WLIH_H = O_WPHH_L + SZ_W256;
static constexpr size_t O_WLIH_L = O_WLIH_H + SZ_W512;
static constexpr size_t O_WLHH_H = O_WLIH_L + SZ_W512;
static constexpr size_t O_WLHH_L = O_WLHH_H + SZ_W256;
static constexpr size_t O_WRIH_H = O_WLHH_L + SZ_W256;
static constexpr size_t O_WRIH_L = O_WRIH_H + SZ_W512;
static constexpr size_t O_WRHH_H = O_WRIH_L + SZ_W512;
static constexpr size_t O_WRHH_L = O_WRHH_H + SZ_W256;
static constexpr size_t O_WEIH_H = O_WRHH_L + SZ_W256;
static constexpr size_t O_WEIH_L = O_WEIH_H + SZ_W768;
static constexpr size_t O_WEHH_H = O_WEIH_L + SZ_W768;
static constexpr size_t O_WEHH_L = O_WEHH_H + SZ_W256;
static constexpr size_t O_SELROW = O_WEHH_L + SZ_W256;
static constexpr size_t O_QMIDX  = O_SELROW + BB * 4;
static constexpr size_t POOL_SZ  = O_QMIDX + BB * 4;

__device__ __align__(1024) unsigned char g_pool[POOL_SZ];

// ================= helpers =================
__device__ __forceinline__ void bsplit(float x, __nv_bfloat16* hp, __nv_bfloat16* lp, size_t i) {
    __nv_bfloat16 h = __float2bfloat16(x);
    hp[i] = h;
    lp[i] = __float2bfloat16(x - __bfloat162float(h));
}

// ================= conv_all =================
struct ConvSeg { const float* src; __nv_bfloat16* hi; __nv_bfloat16* lo; int nblk; };
struct ConvTable { ConvSeg s[13]; };

__global__ void conv_all_kernel(ConvTable t) {
    int blk = blockIdx.x;
    #pragma unroll 1
    for (int i = 0; i < 13; i++) {
        int nb = t.s[i].nblk;
        if (blk < nb) {
            int idx = blk * 256 + threadIdx.x;
            bsplit(t.s[i].src[idx], t.s[i].hi, t.s[i].lo, idx);
            return;
        }
        blk -= nb;
    }
}

// ================= prep =================
__global__ void prep_kernel(const float* __restrict__ U, const float* __restrict__ qmask,
                            const float* __restrict__ q0, const float* __restrict__ r0,
                            float* __restrict__ qsf, float* __restrict__ rsf,
                            __nv_bfloat16* qsh, __nv_bfloat16* qsl,
                            __nv_bfloat16* rsh, __nv_bfloat16* rsl,
                            __nv_bfloat16* xgh, __nv_bfloat16* xgl,
                            __nv_bfloat16* xqsh, __nv_bfloat16* xqsl,
                            __nv_bfloat16* xrsh, __nv_bfloat16* xrsl,
                            __nv_bfloat16* xplh, __nv_bfloat16* xpll,
                            __nv_bfloat16* xeh,  __nv_bfloat16* xel,
                            int* __restrict__ selrow, int* __restrict__ qmidx) {
    int i = blockIdx.x * 256 + threadIdx.x;
    int b = i >> 8, d = i & 255;
    int qm = (qmask[b * 2 + 1] > qmask[b * 2]) ? 1 : 0;
    if (d == 0) { qmidx[b] = qm; selrow[b] = b * 2 + qm; }
    float q = q0[(size_t)(b * 2 + qm) * DD + d];
    float r = r0[(size_t)(b * 2 + qm) * DD + d];
    float u = U[i];
    qsf[i] = q; rsf[i] = r;
    bsplit(q, qsh, qsl, i);
    bsplit(r, rsh, rsl, i);
    size_t o = (size_t)b * 768 + d;
    bsplit(q, xgh, xgl, o);
    bsplit(r, xgh, xgl, o + 256);
    bsplit(u, xgh, xgl, o + 512);
    size_t o2 = (size_t)b * 512 + 256 + d;
    bsplit(u, xqsh, xqsl, o2);
    bsplit(u, xrsh, xrsl, o2);
    bsplit(u, xplh, xpll, o2);
    bsplit(u, xeh, xel, o);
}

// ================= attention =================
__global__ void att_kernel(const float* __restrict__ gh, const float* __restrict__ attw,
                           __nv_bfloat16* __restrict__ xrsh, __nv_bfloat16* __restrict__ xrsl,
                           float* __restrict__ alpha_out) {
    extern __shared__ float sh[];
    __shared__ float s_aw[DD];
    __shared__ float s_scale[TT];
    __shared__ float s_alpha[TT];
    int b = blockIdx.x, tid = threadIdx.x;
    s_aw[tid] = attw[tid];
    for (int t = 0; t < TT; t++)
        sh[t * DD + tid] = gh[((size_t)t * BB + b) * DD + tid];
    __syncthreads();
    int w = tid >> 5, lane = tid & 31;
    for (int t = w; t < TT; t += 8) {
        float s = 0.f;
        #pragma unroll
        for (int i = 0; i < 8; i++) s += sh[t * DD + lane + i * 32] * s_aw[lane + i * 32];
        #pragma unroll
        for (int o = 16; o > 0; o >>= 1) s += __shfl_down_sync(0xffffffffu, s, o);
        if (lane == 0) s_scale[t] = s;
    }
    __syncthreads();
    if (w == 0) {
        float v0 = s_scale[lane], v1 = s_scale[lane + 32];
        float m = fmaxf(v0, v1);
        #pragma unroll
        for (int o = 16; o > 0; o >>= 1) m = fmaxf(m, __shfl_xor_sync(0xffffffffu, m, o));
        float e0 = expf(v0 - m), e1 = expf(v1 - m);
        float s = e0 + e1;
        #pragma unroll
        for (int o = 16; o > 0; o >>= 1) s += __shfl_xor_sync(0xffffffffu, s, o);
        float inv = 1.f / s;
        s_alpha[lane] = e0 * inv;
        s_alpha[lane + 32] = e1 * inv;
        alpha_out[(size_t)b * TT + lane] = e0 * inv;
        alpha_out[(size_t)b * TT + lane + 32] = e1 * inv;
    }
    __syncthreads();
    float acc = 0.f;
    for (int t = 0; t < TT; t++) acc += s_alpha[t] * sh[t * DD + tid];
    bsplit(acc, xrsh, xrsl, (size_t)b * 512 + tid);
}

// ================= fused GRU via mma.sync — static acc, 64x32 block, 3 CTAs/SM ====
// Block tile: 64 rows x 32 out-cols; 8 warps = 4(m) x 2(n); warp tile 16x16.
// Smem stage: A-hi(5120) A-lo(5120) W[g0 hi|g0 lo|g1 hi|g1 lo|g2 hi|g2 lo](6x2560).
// Stage = 25600 B, double-buffered = 51200 B. acc[4][8] (32 f32), all indices static.
#define ATILE 5120
#define WREG  10240
#define STAGE_SB 25600
#define GRU_SMEM (2 * STAGE_SB)

// one gate x one A-term group: 2 MMAs (two n-subtiles)
#define GATE2(ACCP, AF, BR) do { \
    mma16816((ACCP),     (AF), (BR)[0], (BR)[1]); \
    mma16816((ACCP) + 4, (AF), (BR)[2], (BR)[3]); \
} while (0)

__global__ __launch_bounds__(256, 3) void gru_mma_kernel(
    const __nv_bfloat16* __restrict__ Xhi, const __nv_bfloat16* __restrict__ Xlo,
    int K, int xshift,
    const __nv_bfloat16* __restrict__ Hhi, const __nv_bfloat16* __restrict__ Hlo,
    const float* __restrict__ Hf,
    const __nv_bfloat16* __restrict__ Wih_hi, const __nv_bfloat16* __restrict__ Wih_lo,
    const __nv_bfloat16* __restrict__ Whh_hi, const __nv_bfloat16* __restrict__ Whh_lo,
    const float* __restrict__ bih, const float* __restrict__ bhh,
    float* __restrict__ Out, const int* __restrict__ out_rows,
    const int* __restrict__ selrow, int zero_other,
    __nv_bfloat16* __restrict__ x1h, __nv_bfloat16* __restrict__ x1l,
    int x1_stride, int x1_off, int x1_sel,
    __nv_bfloat16* __restrict__ x2h, __nv_bfloat16* __restrict__ x2l,
    int x2_stride, int x2_off)
{
    extern __shared__ __align__(16) char dsm[];
    const uint32_t smb = smem_u32(dsm);

    const int tid = threadIdx.x;
    const int wid = tid >> 5, lane = tid & 31;
    const int warp_m = wid & 3, warp_n = wid >> 2;
    const int row0 = blockIdx.x * 64, c0 = blockIdx.y * 32;

    const int nch0 = K / 32;
    const int ntot = nch0 + 8;

    float a0[8] = {}, a1[8] = {}, a2[8] = {}, a3[8] = {};

    // ---- loader setup: 5 vectors/thread/chunk ----
    const int lr = tid >> 2, lcv = tid & 3;
    const uint32_t sA = (uint32_t)lr * 80 + lcv * 16;   // relative smem offsets
    uint32_t sW[3];
    int wgi[3], whl[3], wri[3], wci[3];
    #pragma unroll
    for (int j = 0; j < 3; j++) {
        int v = tid + 256 * j;          // 0..767
        int rrow = v >> 2, c = v & 3;   // region row 0..191
        sW[j] = WREG + (uint32_t)rrow * 80 + c * 16;
        int tile = rrow >> 5;           // 0..5
        wgi[j] = tile >> 1; whl[j] = tile & 1; wri[j] = rrow & 31; wci[j] = c;
    }
    const __nv_bfloat16* pa  = Xhi + (size_t)((row0 + lr) >> xshift) * K + lcv * 8;
    const __nv_bfloat16* pal = Xlo + (size_t)((row0 + lr) >> xshift) * K + lcv * 8;
    const __nv_bfloat16* pw[3];
    #pragma unroll
    for (int j = 0; j < 3; j++)
        pw[j] = (whl[j] ? Wih_lo : Wih_hi)
              + (size_t)(wgi[j] * 256 + c0 + wri[j]) * K + wci[j] * 8;

    // ---- ldsm lane offsets (relative) ----
    const uint32_t AOFF = ((uint32_t)(warp_m * 16 + (lane & 7) + ((lane >> 3) & 1) * 8)) * 80
                        + (uint32_t)(lane >> 4) * 16;
    const uint32_t BOFF = WREG
                        + ((uint32_t)(warp_n * 16 + (lane & 7) + (lane >> 4) * 8)) * 80
                        + (uint32_t)((lane >> 3) & 1) * 16;

    #define PREF(SOFF) do { \
        cp16(smb + (SOFF) + sA,         pa); \
        cp16(smb + (SOFF) + sA + ATILE, pal); \
        cp16(smb + (SOFF) + sW[0], pw[0]); \
        cp16(smb + (SOFF) + sW[1], pw[1]); \
        cp16(smb + (SOFF) + sW[2], pw[2]); \
        pa += 32; pal += 32; pw[0] += 32; pw[1] += 32; pw[2] += 32; \
    } while (0)

    PREF(0);
    asm volatile("cp.async.commit_group;");

    #pragma unroll 1
    for (int i = 0; i < ntot; i++) {
        if (i + 1 < ntot) {
            if (i + 1 == nch0) {   // switch to hidden GEMM sources
                pa  = Hhi + (size_t)(row0 + lr) * 256 + lcv * 8;
                pal = Hlo + (size_t)(row0 + lr) * 256 + lcv * 8;
                #pragma unroll
                for (int j = 0; j < 3; j++)
                    pw[j] = (whl[j] ? Whh_lo : Whh_hi)
                          + (size_t)(wgi[j] * 256 + c0 + wri[j]) * 256 + wci[j] * 8;
            }
            PREF(((i + 1) & 1) ? STAGE_SB : 0u);
        }
        asm volatile("cp.async.commit_group;");
        asm volatile("cp.async.wait_group 1;");
        __syncthreads();

        const uint32_t base = smb + ((i & 1) ? STAGE_SB : 0u);
        if (i < nch0) {
            // phase 0: gates r->a0, z->a1, in->a2
            #pragma unroll
            for (int s = 0; s < 2; s++) {
                const uint32_t ka = (uint32_t)s * 32;
                uint32_t ah[4], al[4], bh[4], bl[4];
                ldsm4(ah, base + AOFF + ka);
                ldsm4(al, base + AOFF + ATILE + ka);
                ldsm4(bh, base + BOFF + ka);
                ldsm4(bl, base + BOFF + 2560 + ka);
                GATE2(a0, ah, bh); GATE2(a0, ah, bl); GATE2(a0, al, bh);
                ldsm4(bh, base + BOFF + 5120 + ka);
                ldsm4(bl, base + BOFF + 7680 + ka);
                GATE2(a1, ah, bh); GATE2(a1, ah, bl); GATE2(a1, al, bh);
                ldsm4(bh, base + BOFF + 10240 + ka);
                ldsm4(bl, base + BOFF + 12800 + ka);
                GATE2(a2, ah, bh); GATE2(a2, ah, bl); GATE2(a2, al, bh);
            }
        } else {
            // phase 1: gates r->a0, z->a1, hn->a3
            #pragma unroll
            for (int s = 0; s < 2; s++) {
                const uint32_t ka = (uint32_t)s * 32;
                uint32_t ah[4], al[4], bh[4], bl[4];
                ldsm4(ah, base + AOFF + ka);
                ldsm4(al, base + AOFF + ATILE + ka);
                ldsm4(bh, base + BOFF + ka);
                ldsm4(bl, base + BOFF + 2560 + ka);
                GATE2(a0, ah, bh); GATE2(a0, ah, bl); GATE2(a0, al, bh);
                ldsm4(bh, base + BOFF + 5120 + ka);
                ldsm4(bl, base + BOFF + 7680 + ka);
                GATE2(a1, ah, bh); GATE2(a1, ah, bl); GATE2(a1, al, bh);
                ldsm4(bh, base + BOFF + 10240 + ka);
                ldsm4(bl, base + BOFF + 12800 + ka);
                GATE2(a3, ah, bh); GATE2(a3, ah, bl); GATE2(a3, al, bh);
            }
        }
        __syncthreads();
    }
    #undef PREF

    // ---- epilogue ----
    const int mrow = row0 + warp_m * 16 + (lane >> 2);
    const int colbase = c0 + warp_n * 16 + (lane & 3) * 2;
    #pragma unroll
    for (int half = 0; half < 2; half++) {
        int m = mrow + half * 8;
        int orow = out_rows ? out_rows[m] : m;
        const float* hrow = Hf + (size_t)m * 256;
        float* op = Out + (size_t)orow * 256;
        float* oo = zero_other ? (Out + (size_t)(orow ^ 1) * 256) : nullptr;
        int x1b = x1_sel ? (m >> 1) : m;
        bool x1ok = x1h && (!x1_sel || (selrow[x1b] == m));
        #pragma unroll
        for (int nt = 0; nt < 2; nt++) {
            #pragma unroll
            for (int e = 0; e < 2; e++) {
                int col = colbase + nt * 8 + e;
                int d = nt * 4 + half * 2 + e;
                float ar = a0[d] + bih[col] + bhh[col];
                float az = a1[d] + bih[256 + col] + bhh[256 + col];
                float r = 1.f / (1.f + expf(-ar));
                float z = 1.f / (1.f + expf(-az));
                float n = tanhf(a2[d] + bih[512 + col] + r * (a3[d] + bhh[512 + col]));
                float v = (1.f - z) * n + z * hrow[col];
                op[col] = v;
                if (oo) oo[col] = 0.f;
                if (x1ok) bsplit(v, x1h, x1l, (size_t)x1b * x1_stride + x1_off + col);
                if (x2h)  bsplit(v, x2h, x2l, (size_t)m * x2_stride + x2_off + col);
            }
        }
    }
}

// ================= launch =================
extern "C" void kernel_launch(void* const* d_in, const int* in_sizes, int n_in,
                              void* d_out, int out_size) {
    const float* U      = (const float*)d_in[0];
    const float* qmask  = (const float*)d_in[1];
    const float* g_hist = (const float*)d_in[2];
    const float* q0     = (const float*)d_in[3];
    const float* r0     = (const float*)d_in[4];
    const float* e0     = (const float*)d_in[5];
    const float* g_wih  = (const float*)d_in[6];
    const float* g_whh  = (const float*)d_in[7];
    const float* g_bih  = (const float*)d_in[8];
    const float* g_bhh  = (const float*)d_in[9];
    const float* p_wih  = (const float*)d_in[10];
    const float* p_whh  = (const float*)d_in[11];
    const float* p_bih  = (const float*)d_in[12];
    const float* p_bhh  = (const float*)d_in[13];
    const float* pl_wih = (const float*)d_in[14];
    const float* pl_whh = (const float*)d_in[15];
    const float* pl_bih = (const float*)d_in[16];
    const float* pl_bhh = (const float*)d_in[17];
    const float* r_wih  = (const float*)d_in[18];
    const float* r_whh  = (const float*)d_in[19];
    const float* r_bih  = (const float*)d_in[20];
    const float* r_bhh  = (const float*)d_in[21];
    const float* e_wih  = (const float*)d_in[22];
    const float* e_whh  = (const float*)d_in[23];
    const float* e_bih  = (const float*)d_in[24];
    const float* e_bhh  = (const float*)d_in[25];
    const float* att_w  = (const float*)d_in[26];

    float* out = (float*)d_out;
    float* o_g = out;
    float* o_q = out + 1048576;
    float* o_r = out + 3145728;
    float* o_e = out + 5242880;
    float* o_a = out + 6291456;

    void* poolv;
    cudaGetSymbolAddress(&poolv, g_pool);
    char* pool = (char*)poolv;
    #define BF(off) ((__nv_bfloat16*)(pool + (off)))
    #define FP(off) ((float*)(pool + (off)))
    int* selrow = (int*)(pool + O_SELROW);
    int* qmidx  = (int*)(pool + O_QMIDX);

    cudaFuncSetAttribute(att_kernel, cudaFuncAttributeMaxDynamicSharedMemorySize,
                         TT * DD * (int)sizeof(float));
    cudaFuncSetAttribute(gru_mma_kernel, cudaFuncAttributeMaxDynamicSharedMemorySize, GRU_SMEM);

    const float* ghl = g_hist + (size_t)63 * BB * DD;

    // 1) conversions
    ConvTable ct;
    int ti = 0, total_blk = 0;
    auto addseg = [&](const float* s, size_t oh, size_t ol, int n) {
        ct.s[ti].src = s; ct.s[ti].hi = BF(oh); ct.s[ti].lo = BF(ol);
        ct.s[ti].nblk = n / 256; total_blk += n / 256; ti++;
    };
    addseg(g_wih,  O_WGIH_H, O_WGIH_L, 768 * 768);
    addseg(g_whh,  O_WGHH_H, O_WGHH_L, 768 * 256);
    addseg(p_wih,  O_WPIH_H, O_WPIH_L, 768 * 512);
    addseg(p_whh,  O_WPHH_H, O_WPHH_L, 768 * 256);
    addseg(pl_wih, O_WLIH_H, O_WLIH_L, 768 * 512);
    addseg(pl_whh, O_WLHH_H, O_WLHH_L, 768 * 256);
    addseg(r_wih,  O_WRIH_H, O_WRIH_L, 768 * 512);
    addseg(r_whh,  O_WRHH_H, O_WRHH_L, 768 * 256);
    addseg(e_wih,  O_WEIH_H, O_WEIH_L, 768 * 768);
    addseg(e_whh,  O_WEHH_H, O_WEHH_L, 768 * 256);
    addseg(q0,     O_Q0_H,   O_Q0_L,   2 * BB * 256);
    addseg(ghl,    O_GH_H,   O_GH_L,   BB * 256);
    addseg(e0,     O_E0_H,   O_E0_L,   BB * 256);
    conv_all_kernel<<<total_blk, 256>>>(ct);

    // 2) prep
    prep_kernel<<<BB, 256>>>(U, qmask, q0, r0,
        FP(O_QSF), FP(O_RSF), BF(O_QS_H), BF(O_QS_L), BF(O_RS_H), BF(O_RS_L),
        BF(O_XG_H), BF(O_XG_L),
        BF(O_XQS_H), BF(O_XQS_L), BF(O_XRS_H), BF(O_XRS_L),
        BF(O_XPL_H), BF(O_XPL_L), BF(O_XE_H), BF(O_XE_L),
        selrow, qmidx);

    // 3) attention -> xrs first half + alpha
    att_kernel<<<BB, 256, TT * DD * sizeof(float)>>>(g_hist, att_w,
        BF(O_XRS_H), BF(O_XRS_L), o_a);

    // 4) g GRU: K=768; epilogue writes xqs[0:256] and xe[512:768]
    gru_mma_kernel<<<dim3(BB / 64, 8), 256, GRU_SMEM>>>(
        BF(O_XG_H), BF(O_XG_L), 768, 0,
        BF(O_GH_H), BF(O_GH_L), ghl,
        BF(O_WGIH_H), BF(O_WGIH_L), BF(O_WGHH_H), BF(O_WGHH_L),
        g_bih, g_bhh, o_g, nullptr,
        nullptr, 0,
        BF(O_XQS_H), BF(O_XQS_L), 512, 0, 0,
        BF(O_XE_H), BF(O_XE_L), 768, 512);

    // 5) qs GRU: 8192 rows; epilogue writes xpl[0:256] for selected rows
    gru_mma_kernel<<<dim3(2 * BB / 64, 8), 256, GRU_SMEM>>>(
        BF(O_XQS_H), BF(O_XQS_L), 512, 1,
        BF(O_Q0_H), BF(O_Q0_L), q0,
        BF(O_WPIH_H), BF(O_WPIH_L), BF(O_WPHH_H), BF(O_WPHH_L),
        p_bih, p_bhh, o_q, nullptr,
        selrow, 0,
        BF(O_XPL_H), BF(O_XPL_L), 512, 0, 1,
        nullptr, nullptr, 0, 0);

    // 6) rs GRU: selected rows, scatter + zero sibling row   [ncu slot 6]
    gru_mma_kernel<<<dim3(BB / 64, 8), 256, GRU_SMEM>>>(
        BF(O_XRS_H), BF(O_XRS_L), 512, 0,
        BF(O_RS_H), BF(O_RS_L), FP(O_RSF),
        BF(O_WRIH_H), BF(O_WRIH_L), BF(O_WRHH_H), BF(O_WRHH_L),
        r_bih, r_bhh, o_r, selrow,
        nullptr, 1,
        nullptr, nullptr, 0, 0, 0,
        nullptr, nullptr, 0, 0);

    // 7) ql GRU: selected rows, scatter into q_; epilogue writes xe[256:512]
    gru_mma_kernel<<<dim3(BB / 64, 8), 256, GRU_SMEM>>>(
        BF(O_XPL_H), BF(O_XPL_L), 512, 0,
        BF(O_QS_H), BF(O_QS_L), FP(O_QSF),
        BF(O_WLIH_H), BF(O_WLIH_L), BF(O_WLHH_H), BF(O_WLHH_L),
        pl_bih, pl_bhh, o_q, selrow,
        nullptr, 0,
        BF(O_XE_H), BF(O_XE_L), 768, 256, 0,
        nullptr, nullptr, 0, 0);

    // 8) e GRU: K=768
    gru_mma_kernel<<<dim3(BB / 64, 8), 256, GRU_SMEM>>>(
        BF(O_XE_H), BF(O_XE_L), 768, 0,
        BF(O_E0_H), BF(O_E0_L), e0,
        BF(O_WEIH_H), BF(O_WEIH_L), BF(O_WEHH_H), BF(O_WEHH_L),
        e_bih, e_bhh, o_e, nullptr,
        nullptr, 0,
        nullptr, nullptr, 0, 0, 0,
        nullptr, nullptr, 0, 0);
    #undef BF
    #undef FP
}

// round 10
// speedup vs baseline: 1.7274x; 1.0472x over previous
#include <cuda_runtime.h>
#include <cuda_bf16.h>
#include <math.h>
#include <stdint.h>

#define BB 4096
#define DD 256
#define TT 64

// ================= PTX helpers (baseline ISA only) =================
__device__ __forceinline__ uint32_t smem_u32(const void* p) {
    uint32_t a;
    asm("{ .reg .u64 t; cvta.to.shared.u64 t, %1; cvt.u32.u64 %0, t; }" : "=r"(a) : "l"(p));
    return a;
}
__device__ __forceinline__ void cp16(uint32_t saddr, const void* g) {
    asm volatile("cp.async.cg.shared.global [%0], [%1], 16;" :: "r"(saddr), "l"(g));
}
__device__ __forceinline__ void ldsm4(uint32_t* r, uint32_t addr) {
    asm volatile("ldmatrix.sync.aligned.m8n8.x4.shared.b16 {%0,%1,%2,%3}, [%4];"
        : "=r"(r[0]), "=r"(r[1]), "=r"(r[2]), "=r"(r[3]) : "r"(addr));
}
__device__ __forceinline__ void mma16816(float* c, const uint32_t* a, uint32_t b0, uint32_t b1) {
    asm volatile("mma.sync.aligned.m16n8k16.row.col.f32.bf16.bf16.f32 "
        "{%0,%1,%2,%3}, {%4,%5,%6,%7}, {%8,%9}, {%0,%1,%2,%3};"
        : "+f"(c[0]), "+f"(c[1]), "+f"(c[2]), "+f"(c[3])
        : "r"(a[0]), "r"(a[1]), "r"(a[2]), "r"(a[3]), "r"(b0), "r"(b1));
}

// ================= scratch pool =================
static constexpr size_t SZ_XG  = (size_t)BB * 768 * 2;
static constexpr size_t SZ_XS  = (size_t)BB * 512 * 2;
static constexpr size_t SZ_BD  = (size_t)BB * 256 * 2;
static constexpr size_t SZ_Q0  = (size_t)2 * BB * 256 * 2;
static constexpr size_t SZ_BDF = (size_t)BB * 256 * 4;

static constexpr size_t O_XG_H  = 0;
static constexpr size_t O_XG_L  = O_XG_H  + SZ_XG;
static constexpr size_t O_XE_H  = O_XG_L  + SZ_XG;
static constexpr size_t O_XE_L  = O_XE_H  + SZ_XG;
static constexpr size_t O_XQS_H = O_XE_L  + SZ_XG;
static constexpr size_t O_XQS_L = O_XQS_H + SZ_XS;
static constexpr size_t O_XRS_H = O_XQS_L + SZ_XS;
static constexpr size_t O_XRS_L = O_XRS_H + SZ_XS;
static constexpr size_t O_XPL_H = O_XRS_L + SZ_XS;
static constexpr size_t O_XPL_L = O_XPL_H + SZ_XS;
static constexpr size_t O_Q0_H  = O_XPL_L + SZ_XS;
static constexpr size_t O_Q0_L  = O_Q0_H  + SZ_Q0;
static constexpr size_t O_GH_H  = O_Q0_L  + SZ_Q0;
static constexpr size_t O_GH_L  = O_GH_H  + SZ_BD;
static constexpr size_t O_E0_H  = O_GH_L  + SZ_BD;
static constexpr size_t O_E0_L  = O_E0_H  + SZ_BD;
static constexpr size_t O_QS_H  = O_E0_L  + SZ_BD;
static constexpr size_t O_QS_L  = O_QS_H  + SZ_BD;
static constexpr size_t O_RS_H  = O_QS_L  + SZ_BD;
static constexpr size_t O_RS_L  = O_RS_H  + SZ_BD;
static constexpr size_t O_QSF   = O_RS_L  + SZ_BD;
static constexpr size_t O_RSF   = O_QSF   + SZ_BDF;
static constexpr size_t SZ_W768 = (size_t)768 * 768 * 2;
static constexpr size_t SZ_W512 = (size_t)768 * 512 * 2;
static constexpr size_t SZ_W256 = (size_t)768 * 256 * 2;
static constexpr size_t O_WGIH_H = O_RSF + SZ_BDF;
static constexpr size_t O_WGIH_L = O_WGIH_H + SZ_W768;
static constexpr size_t O_WGHH_H = O_WGIH_L + SZ_W768;
static constexpr size_t O_WGHH_L = O_WGHH_H + SZ_W256;
static constexpr size_t O_WPIH_H = O_WGHH_L + SZ_W256;
static constexpr size_t O_WPIH_L = O_WPIH_H + SZ_W512;
static constexpr size_t O_WPHH_H = O_WPIH_L + SZ_W512;
static constexpr size_t O_WPHH_L = O_WPHH_H + SZ_W256;
static constexpr size_t O_WLIH_H = O_WPHH_L + SZ_W256;
static constexpr size_t O_WLIH_L = O_WLIH_H + SZ_W512;
static constexpr size_t O_WLHH_H = O_WLIH_L + SZ_W512;
static constexpr size_t O_WLHH_L = O_WLHH_H + SZ_W256;
static constexpr size_t O_WRIH_H = O_WLHH_L + SZ_W256;
static constexpr size_t O_WRIH_L = O_WRIH_H + SZ_W512;
static constexpr size_t O_WRHH_H = O_WRIH_L + SZ_W512;
static constexpr size_t O_WRHH_L = O_WRHH_H + SZ_W256;
static constexpr size_t O_WEIH_H = O_WRHH_L + SZ_W256;
static constexpr size_t O_WEIH_L = O_WEIH_H + SZ_W768;
static constexpr size_t O_WEHH_H = O_WEIH_L + SZ_W768;
static constexpr size_t O_WEHH_L = O_WEHH_H + SZ_W256;
static constexpr size_t O_SELROW = O_WEHH_L + SZ_W256;
static constexpr size_t O_QMIDX  = O_SELROW + BB * 4;
static constexpr size_t POOL_SZ  = O_QMIDX + BB * 4;

__device__ __align__(1024) unsigned char g_pool[POOL_SZ];

// ================= helpers =================
__device__ __forceinline__ void bsplit(float x, __nv_bfloat16* hp, __nv_bfloat16* lp, size_t i) {
    __nv_bfloat16 h = __float2bfloat16(x);
    hp[i] = h;
    lp[i] = __float2bfloat16(x - __bfloat162float(h));
}

// ================= conv_all: vectorized x4 =================
struct ConvSeg { const float* src; __nv_bfloat16* hi; __nv_bfloat16* lo; int nblk; };
struct ConvTable { ConvSeg s[13]; };

__global__ void conv_all_kernel(ConvTable t) {
    int blk = blockIdx.x;
    #pragma unroll 1
    for (int i = 0; i < 13; i++) {
        int nb = t.s[i].nblk;
        if (blk < nb) {
            int idx = blk * 1024 + threadIdx.x * 4;   // 4 elems/thread
            float4 v = *(const float4*)(t.s[i].src + idx);
            __nv_bfloat16 h0 = __float2bfloat16(v.x);
            __nv_bfloat16 h1 = __float2bfloat16(v.y);
            __nv_bfloat16 h2 = __float2bfloat16(v.z);
            __nv_bfloat16 h3 = __float2bfloat16(v.w);
            __nv_bfloat16 l0 = __float2bfloat16(v.x - __bfloat162float(h0));
            __nv_bfloat16 l1 = __float2bfloat16(v.y - __bfloat162float(h1));
            __nv_bfloat16 l2 = __float2bfloat16(v.z - __bfloat162float(h2));
            __nv_bfloat16 l3 = __float2bfloat16(v.w - __bfloat162float(h3));
            __nv_bfloat162 hv0, hv1, lv0, lv1;
            hv0.x = h0; hv0.y = h1; hv1.x = h2; hv1.y = h3;
            lv0.x = l0; lv0.y = l1; lv1.x = l2; lv1.y = l3;
            *(__nv_bfloat162*)(t.s[i].hi + idx)     = hv0;
            *(__nv_bfloat162*)(t.s[i].hi + idx + 2) = hv1;
            *(__nv_bfloat162*)(t.s[i].lo + idx)     = lv0;
            *(__nv_bfloat162*)(t.s[i].lo + idx + 2) = lv1;
            return;
        }
        blk -= nb;
    }
}

// ================= prep =================
__global__ void prep_kernel(const float* __restrict__ U, const float* __restrict__ qmask,
                            const float* __restrict__ q0, const float* __restrict__ r0,
                            float* __restrict__ qsf, float* __restrict__ rsf,
                            __nv_bfloat16* qsh, __nv_bfloat16* qsl,
                            __nv_bfloat16* rsh, __nv_bfloat16* rsl,
                            __nv_bfloat16* xgh, __nv_bfloat16* xgl,
                            __nv_bfloat16* xqsh, __nv_bfloat16* xqsl,
                            __nv_bfloat16* xrsh, __nv_bfloat16* xrsl,
                            __nv_bfloat16* xplh, __nv_bfloat16* xpll,
                            __nv_bfloat16* xeh,  __nv_bfloat16* xel,
                            int* __restrict__ selrow, int* __restrict__ qmidx) {
    int i = blockIdx.x * 256 + threadIdx.x;
    int b = i >> 8, d = i & 255;
    int qm = (qmask[b * 2 + 1] > qmask[b * 2]) ? 1 : 0;
    if (d == 0) { qmidx[b] = qm; selrow[b] = b * 2 + qm; }
    float q = q0[(size_t)(b * 2 + qm) * DD + d];
    float r = r0[(size_t)(b * 2 + qm) * DD + d];
    float u = U[i];
    qsf[i] = q; rsf[i] = r;
    bsplit(q, qsh, qsl, i);
    bsplit(r, rsh, rsl, i);
    size_t o = (size_t)b * 768 + d;
    bsplit(q, xgh, xgl, o);
    bsplit(r, xgh, xgl, o + 256);
    bsplit(u, xgh, xgl, o + 512);
    size_t o2 = (size_t)b * 512 + 256 + d;
    bsplit(u, xqsh, xqsl, o2);
    bsplit(u, xrsh, xrsl, o2);
    bsplit(u, xplh, xpll, o2);
    bsplit(u, xeh, xel, o);
}

// ================= attention =================
__global__ void att_kernel(const float* __restrict__ gh, const float* __restrict__ attw,
                           __nv_bfloat16* __restrict__ xrsh, __nv_bfloat16* __restrict__ xrsl,
                           float* __restrict__ alpha_out) {
    extern __shared__ float sh[];
    __shared__ float s_aw[DD];
    __shared__ float s_scale[TT];
    __shared__ float s_alpha[TT];
    int b = blockIdx.x, tid = threadIdx.x;
    s_aw[tid] = attw[tid];
    for (int t = 0; t < TT; t++)
        sh[t * DD + tid] = gh[((size_t)t * BB + b) * DD + tid];
    __syncthreads();
    int w = tid >> 5, lane = tid & 31;
    for (int t = w; t < TT; t += 8) {
        float s = 0.f;
        #pragma unroll
        for (int i = 0; i < 8; i++) s += sh[t * DD + lane + i * 32] * s_aw[lane + i * 32];
        #pragma unroll
        for (int o = 16; o > 0; o >>= 1) s += __shfl_down_sync(0xffffffffu, s, o);
        if (lane == 0) s_scale[t] = s;
    }
    __syncthreads();
    if (w == 0) {
        float v0 = s_scale[lane], v1 = s_scale[lane + 32];
        float m = fmaxf(v0, v1);
        #pragma unroll
        for (int o = 16; o > 0; o >>= 1) m = fmaxf(m, __shfl_xor_sync(0xffffffffu, m, o));
        float e0 = expf(v0 - m), e1 = expf(v1 - m);
        float s = e0 + e1;
        #pragma unroll
        for (int o = 16; o > 0; o >>= 1) s += __shfl_xor_sync(0xffffffffu, s, o);
        float inv = 1.f / s;
        s_alpha[lane] = e0 * inv;
        s_alpha[lane + 32] = e1 * inv;
        alpha_out[(size_t)b * TT + lane] = e0 * inv;
        alpha_out[(size_t)b * TT + lane + 32] = e1 * inv;
    }
    __syncthreads();
    float acc = 0.f;
    for (int t = 0; t < TT; t++) acc += s_alpha[t] * sh[t * DD + tid];
    bsplit(acc, xrsh, xrsl, (size_t)b * 512 + tid);
}

// ================= fused GRU via mma.sync — single barrier per chunk =================
// Block tile: 64 rows x 32 out-cols; 8 warps = 4(m) x 2(n); warp tile 16x16.
// Stage = 25600 B x2. One __syncthreads per chunk:
//   wait_group 0 -> BARRIER -> prefetch(i+1) -> consume(i)
// The barrier both publishes stage i and certifies stage (i+1)&1 fully consumed.
#define ATILE 5120
#define WREG  10240
#define STAGE_SB 25600
#define GRU_SMEM (2 * STAGE_SB)

#define GATE2(ACCP, AF, BR) do { \
    mma16816((ACCP),     (AF), (BR)[0], (BR)[1]); \
    mma16816((ACCP) + 4, (AF), (BR)[2], (BR)[3]); \
} while (0)

__global__ __launch_bounds__(256, 3) void gru_mma_kernel(
    const __nv_bfloat16* __restrict__ Xhi, const __nv_bfloat16* __restrict__ Xlo,
    int K, int xshift,
    const __nv_bfloat16* __restrict__ Hhi, const __nv_bfloat16* __restrict__ Hlo,
    const float* __restrict__ Hf,
    const __nv_bfloat16* __restrict__ Wih_hi, const __nv_bfloat16* __restrict__ Wih_lo,
    const __nv_bfloat16* __restrict__ Whh_hi, const __nv_bfloat16* __restrict__ Whh_lo,
    const float* __restrict__ bih, const float* __restrict__ bhh,
    float* __restrict__ Out, const int* __restrict__ out_rows,
    const int* __restrict__ selrow, int zero_other,
    __nv_bfloat16* __restrict__ x1h, __nv_bfloat16* __restrict__ x1l,
    int x1_stride, int x1_off, int x1_sel,
    __nv_bfloat16* __restrict__ x2h, __nv_bfloat16* __restrict__ x2l,
    int x2_stride, int x2_off)
{
    extern __shared__ __align__(16) char dsm[];
    const uint32_t smb = smem_u32(dsm);

    const int tid = threadIdx.x;
    const int wid = tid >> 5, lane = tid & 31;
    const int warp_m = wid & 3, warp_n = wid >> 2;
    const int row0 = blockIdx.x * 64, c0 = blockIdx.y * 32;

    const int nch0 = K / 32;
    const int ntot = nch0 + 8;

    float a0[8] = {}, a1[8] = {}, a2[8] = {}, a3[8] = {};

    // ---- loader setup: 5 vectors/thread/chunk ----
    const int lr = tid >> 2, lcv = tid & 3;
    const uint32_t sA = (uint32_t)lr * 80 + lcv * 16;
    uint32_t sW[3];
    int wgi[3], whl[3], wri[3], wci[3];
    #pragma unroll
    for (int j = 0; j < 3; j++) {
        int v = tid + 256 * j;
        int rrow = v >> 2, c = v & 3;
        sW[j] = WREG + (uint32_t)rrow * 80 + c * 16;
        int tile = rrow >> 5;
        wgi[j] = tile >> 1; whl[j] = tile & 1; wri[j] = rrow & 31; wci[j] = c;
    }
    const __nv_bfloat16* pa  = Xhi + (size_t)((row0 + lr) >> xshift) * K + lcv * 8;
    const __nv_bfloat16* pal = Xlo + (size_t)((row0 + lr) >> xshift) * K + lcv * 8;
    const __nv_bfloat16* pw[3];
    #pragma unroll
    for (int j = 0; j < 3; j++)
        pw[j] = (whl[j] ? Wih_lo : Wih_hi)
              + (size_t)(wgi[j] * 256 + c0 + wri[j]) * K + wci[j] * 8;

    const uint32_t AOFF = ((uint32_t)(warp_m * 16 + (lane & 7) + ((lane >> 3) & 1) * 8)) * 80
                        + (uint32_t)(lane >> 4) * 16;
    const uint32_t BOFF = WREG
                        + ((uint32_t)(warp_n * 16 + (lane & 7) + (lane >> 4) * 8)) * 80
                        + (uint32_t)((lane >> 3) & 1) * 16;

    #define PREF(SOFF) do { \
        cp16(smb + (SOFF) + sA,         pa); \
        cp16(smb + (SOFF) + sA + ATILE, pal); \
        cp16(smb + (SOFF) + sW[0], pw[0]); \
        cp16(smb + (SOFF) + sW[1], pw[1]); \
        cp16(smb + (SOFF) + sW[2], pw[2]); \
        pa += 32; pal += 32; pw[0] += 32; pw[1] += 32; pw[2] += 32; \
    } while (0)

    PREF(0);
    asm volatile("cp.async.commit_group;");

    #pragma unroll 1
    for (int i = 0; i < ntot; i++) {
        asm volatile("cp.async.wait_group 0;");
        __syncthreads();   // publish stage i; certify stage (i+1)&1 consumed

        if (i + 1 < ntot) {
            if (i + 1 == nch0) {
                pa  = Hhi + (size_t)(row0 + lr) * 256 + lcv * 8;
                pal = Hlo + (size_t)(row0 + lr) * 256 + lcv * 8;
                #pragma unroll
                for (int j = 0; j < 3; j++)
                    pw[j] = (whl[j] ? Whh_lo : Whh_hi)
                          + (size_t)(wgi[j] * 256 + c0 + wri[j]) * 256 + wci[j] * 8;
            }
            PREF(((i + 1) & 1) ? STAGE_SB : 0u);
            asm volatile("cp.async.commit_group;");
        }

        const uint32_t base = smb + ((i & 1) ? STAGE_SB : 0u);
        if (i < nch0) {
            #pragma unroll
            for (int s = 0; s < 2; s++) {
                const uint32_t ka = (uint32_t)s * 32;
                uint32_t ah[4], al[4], bh[4], bl[4];
                ldsm4(ah, base + AOFF + ka);
                ldsm4(al, base + AOFF + ATILE + ka);
                ldsm4(bh, base + BOFF + ka);
                ldsm4(bl, base + BOFF + 2560 + ka);
                GATE2(a0, ah, bh); GATE2(a0, ah, bl); GATE2(a0, al, bh);
                ldsm4(bh, base + BOFF + 5120 + ka);
                ldsm4(bl, base + BOFF + 7680 + ka);
                GATE2(a1, ah, bh); GATE2(a1, ah, bl); GATE2(a1, al, bh);
                ldsm4(bh, base + BOFF + 10240 + ka);
                ldsm4(bl, base + BOFF + 12800 + ka);
                GATE2(a2, ah, bh); GATE2(a2, ah, bl); GATE2(a2, al, bh);
            }
        } else {
            #pragma unroll
            for (int s = 0; s < 2; s++) {
                const uint32_t ka = (uint32_t)s * 32;
                uint32_t ah[4], al[4], bh[4], bl[4];
                ldsm4(ah, base + AOFF + ka);
                ldsm4(al, base + AOFF + ATILE + ka);
                ldsm4(bh, base + BOFF + ka);
                ldsm4(bl, base + BOFF + 2560 + ka);
                GATE2(a0, ah, bh); GATE2(a0, ah, bl); GATE2(a0, al, bh);
                ldsm4(bh, base + BOFF + 5120 + ka);
                ldsm4(bl, base + BOFF + 7680 + ka);
                GATE2(a1, ah, bh); GATE2(a1, ah, bl); GATE2(a1, al, bh);
                ldsm4(bh, base + BOFF + 10240 + ka);
                ldsm4(bl, base + BOFF + 12800 + ka);
                GATE2(a3, ah, bh); GATE2(a3, ah, bl); GATE2(a3, al, bh);
            }
        }
    }
    #undef PREF

    // ---- epilogue ----
    const int mrow = row0 + warp_m * 16 + (lane >> 2);
    const int colbase = c0 + warp_n * 16 + (lane & 3) * 2;
    #pragma unroll
    for (int half = 0; half < 2; half++) {
        int m = mrow + half * 8;
        int orow = out_rows ? out_rows[m] : m;
        const float* hrow = Hf + (size_t)m * 256;
        float* op = Out + (size_t)orow * 256;
        float* oo = zero_other ? (Out + (size_t)(orow ^ 1) * 256) : nullptr;
        int x1b = x1_sel ? (m >> 1) : m;
        bool x1ok = x1h && (!x1_sel || (selrow[x1b] == m));
        #pragma unroll
        for (int nt = 0; nt < 2; nt++) {
            #pragma unroll
            for (int e = 0; e < 2; e++) {
                int col = colbase + nt * 8 + e;
                int d = nt * 4 + half * 2 + e;
                float ar = a0[d] + bih[col] + bhh[col];
                float az = a1[d] + bih[256 + col] + bhh[256 + col];
                float r = 1.f / (1.f + expf(-ar));
                float z = 1.f / (1.f + expf(-az));
                float n = tanhf(a2[d] + bih[512 + col] + r * (a3[d] + bhh[512 + col]));
                float v = (1.f - z) * n + z * hrow[col];
                op[col] = v;
                if (oo) oo[col] = 0.f;
                if (x1ok) bsplit(v, x1h, x1l, (size_t)x1b * x1_stride + x1_off + col);
                if (x2h)  bsplit(v, x2h, x2l, (size_t)m * x2_stride + x2_off + col);
            }
        }
    }
}

// ================= launch =================
extern "C" void kernel_launch(void* const* d_in, const int* in_sizes, int n_in,
                              void* d_out, int out_size) {
    const float* U      = (const float*)d_in[0];
    const float* qmask  = (const float*)d_in[1];
    const float* g_hist = (const float*)d_in[2];
    const float* q0     = (const float*)d_in[3];
    const float* r0     = (const float*)d_in[4];
    const float* e0     = (const float*)d_in[5];
    const float* g_wih  = (const float*)d_in[6];
    const float* g_whh  = (const float*)d_in[7];
    const float* g_bih  = (const float*)d_in[8];
    const float* g_bhh  = (const float*)d_in[9];
    const float* p_wih  = (const float*)d_in[10];
    const float* p_whh  = (const float*)d_in[11];
    const float* p_bih  = (const float*)d_in[12];
    const float* p_bhh  = (const float*)d_in[13];
    const float* pl_wih = (const float*)d_in[14];
    const float* pl_whh = (const float*)d_in[15];
    const float* pl_bih = (const float*)d_in[16];
    const float* pl_bhh = (const float*)d_in[17];
    const float* r_wih  = (const float*)d_in[18];
    const float* r_whh  = (const float*)d_in[19];
    const float* r_bih  = (const float*)d_in[20];
    const float* r_bhh  = (const float*)d_in[21];
    const float* e_wih  = (const float*)d_in[22];
    const float* e_whh  = (const float*)d_in[23];
    const float* e_bih  = (const float*)d_in[24];
    const float* e_bhh  = (const float*)d_in[25];
    const float* att_w  = (const float*)d_in[26];

    float* out = (float*)d_out;
    float* o_g = out;
    float* o_q = out + 1048576;
    float* o_r = out + 3145728;
    float* o_e = out + 5242880;
    float* o_a = out + 6291456;

    void* poolv;
    cudaGetSymbolAddress(&poolv, g_pool);
    char* pool = (char*)poolv;
    #define BF(off) ((__nv_bfloat16*)(pool + (off)))
    #define FP(off) ((float*)(pool + (off)))
    int* selrow = (int*)(pool + O_SELROW);
    int* qmidx  = (int*)(pool + O_QMIDX);

    cudaFuncSetAttribute(att_kernel, cudaFuncAttributeMaxDynamicSharedMemorySize,
                         TT * DD * (int)sizeof(float));
    cudaFuncSetAttribute(gru_mma_kernel, cudaFuncAttributeMaxDynamicSharedMemorySize, GRU_SMEM);

    const float* ghl = g_hist + (size_t)63 * BB * DD;

    // 1) conversions (4 elems/thread)
    ConvTable ct;
    int ti = 0, total_blk = 0;
    auto addseg = [&](const float* s, size_t oh, size_t ol, int n) {
        ct.s[ti].src = s; ct.s[ti].hi = BF(oh); ct.s[ti].lo = BF(ol);
        ct.s[ti].nblk = n / 1024; total_blk += n / 1024; ti++;
    };
    addseg(g_wih,  O_WGIH_H, O_WGIH_L, 768 * 768);
    addseg(g_whh,  O_WGHH_H, O_WGHH_L, 768 * 256);
    addseg(p_wih,  O_WPIH_H, O_WPIH_L, 768 * 512);
    addseg(p_whh,  O_WPHH_H, O_WPHH_L, 768 * 256);
    addseg(pl_wih, O_WLIH_H, O_WLIH_L, 768 * 512);
    addseg(pl_whh, O_WLHH_H, O_WLHH_L, 768 * 256);
    addseg(r_wih,  O_WRIH_H, O_WRIH_L, 768 * 512);
    addseg(r_whh,  O_WRHH_H, O_WRHH_L, 768 * 256);
    addseg(e_wih,  O_WEIH_H, O_WEIH_L, 768 * 768);
    addseg(e_whh,  O_WEHH_H, O_WEHH_L, 768 * 256);
    addseg(q0,     O_Q0_H,   O_Q0_L,   2 * BB * 256);
    addseg(ghl,    O_GH_H,   O_GH_L,   BB * 256);
    addseg(e0,     O_E0_H,   O_E0_L,   BB * 256);
    conv_all_kernel<<<total_blk, 256>>>(ct);

    // 2) prep
    prep_kernel<<<BB, 256>>>(U, qmask, q0, r0,
        FP(O_QSF), FP(O_RSF), BF(O_QS_H), BF(O_QS_L), BF(O_RS_H), BF(O_RS_L),
        BF(O_XG_H), BF(O_XG_L),
        BF(O_XQS_H), BF(O_XQS_L), BF(O_XRS_H), BF(O_XRS_L),
        BF(O_XPL_H), BF(O_XPL_L), BF(O_XE_H), BF(O_XE_L),
        selrow, qmidx);

    // 3) attention -> xrs first half + alpha
    att_kernel<<<BB, 256, TT * DD * sizeof(float)>>>(g_hist, att_w,
        BF(O_XRS_H), BF(O_XRS_L), o_a);

    // 4) g GRU: K=768; epilogue writes xqs[0:256] and xe[512:768]
    gru_mma_kernel<<<dim3(BB / 64, 8), 256, GRU_SMEM>>>(
        BF(O_XG_H), BF(O_XG_L), 768, 0,
        BF(O_GH_H), BF(O_GH_L), ghl,
        BF(O_WGIH_H), BF(O_WGIH_L), BF(O_WGHH_H), BF(O_WGHH_L),
        g_bih, g_bhh, o_g, nullptr,
        nullptr, 0,
        BF(O_XQS_H), BF(O_XQS_L), 512, 0, 0,
        BF(O_XE_H), BF(O_XE_L), 768, 512);

    // 5) qs GRU: 8192 rows; epilogue writes xpl[0:256] for selected rows
    gru_mma_kernel<<<dim3(2 * BB / 64, 8), 256, GRU_SMEM>>>(
        BF(O_XQS_H), BF(O_XQS_L), 512, 1,
        BF(O_Q0_H), BF(O_Q0_L), q0,
        BF(O_WPIH_H), BF(O_WPIH_L), BF(O_WPHH_H), BF(O_WPHH_L),
        p_bih, p_bhh, o_q, nullptr,
        selrow, 0,
        BF(O_XPL_H), BF(O_XPL_L), 512, 0, 1,
        nullptr, nullptr, 0, 0);

    // 6) rs GRU: selected rows, scatter + zero sibling row   [ncu slot 6]
    gru_mma_kernel<<<dim3(BB / 64, 8), 256, GRU_SMEM>>>(
        BF(O_XRS_H), BF(O_XRS_L), 512, 0,
        BF(O_RS_H), BF(O_RS_L), FP(O_RSF),
        BF(O_WRIH_H), BF(O_WRIH_L), BF(O_WRHH_H), BF(O_WRHH_L),
        r_bih, r_bhh, o_r, selrow,
        nullptr, 1,
        nullptr, nullptr, 0, 0, 0,
        nullptr, nullptr, 0, 0);

    // 7) ql GRU: selected rows, scatter into q_; epilogue writes xe[256:512]
    gru_mma_kernel<<<dim3(BB / 64, 8), 256, GRU_SMEM>>>(
        BF(O_XPL_H), BF(O_XPL_L), 512, 0,
        BF(O_QS_H), BF(O_QS_L), FP(O_QSF),
        BF(O_WLIH_H), BF(O_WLIH_L), BF(O_WLHH_H), BF(O_WLHH_L),
        pl_bih, pl_bhh, o_q, selrow,
        nullptr, 0,
        BF(O_XE_H), BF(O_XE_L), 768, 256, 0,
        nullptr, nullptr, 0, 0);

    // 8) e GRU: K=768
    gru_mma_kernel<<<dim3(BB / 64, 8), 256, GRU_SMEM>>>(
        BF(O_XE_H), BF(O_XE_L), 768, 0,
        BF(O_E0_H), BF(O_E0_L), e0,
        BF(O_WEIH_H), BF(O_WEIH_L), BF(O_WEHH_H), BF(O_WEHH_L),
        e_bih, e_bhh, o_e, nullptr,
        nullptr, 0,
        nullptr, nullptr, 0, 0, 0,
        nullptr, nullptr, 0, 0);
    #undef BF
    #undef FP
}

// round 11
// speedup vs baseline: 1.8322x; 1.0606x over previous
#include <cuda_runtime.h>
#include <cuda_bf16.h>
#include <math.h>
#include <stdint.h>

#define BB 4096
#define DD 256
#define TT 64

// ================= PTX helpers (baseline ISA only) =================
__device__ __forceinline__ uint32_t smem_u32(const void* p) {
    uint32_t a;
    asm("{ .reg .u64 t; cvta.to.shared.u64 t, %1; cvt.u32.u64 %0, t; }" : "=r"(a) : "l"(p));
    return a;
}
__device__ __forceinline__ void cp16(uint32_t saddr, const void* g) {
    asm volatile("cp.async.cg.shared.global [%0], [%1], 16;" :: "r"(saddr), "l"(g));
}
__device__ __forceinline__ void ldsm4(uint32_t* r, uint32_t addr) {
    asm volatile("ldmatrix.sync.aligned.m8n8.x4.shared.b16 {%0,%1,%2,%3}, [%4];"
        : "=r"(r[0]), "=r"(r[1]), "=r"(r[2]), "=r"(r[3]) : "r"(addr));
}
__device__ __forceinline__ void mma16816(float* c, const uint32_t* a, uint32_t b0, uint32_t b1) {
    asm volatile("mma.sync.aligned.m16n8k16.row.col.f32.bf16.bf16.f32 "
        "{%0,%1,%2,%3}, {%4,%5,%6,%7}, {%8,%9}, {%0,%1,%2,%3};"
        : "+f"(c[0]), "+f"(c[1]), "+f"(c[2]), "+f"(c[3])
        : "r"(a[0]), "r"(a[1]), "r"(a[2]), "r"(a[3]), "r"(b0), "r"(b1));
}

// ================= scratch pool =================
static constexpr size_t SZ_XG  = (size_t)BB * 768 * 2;
static constexpr size_t SZ_XS  = (size_t)BB * 512 * 2;
static constexpr size_t SZ_BD  = (size_t)BB * 256 * 2;
static constexpr size_t SZ_Q0  = (size_t)2 * BB * 256 * 2;
static constexpr size_t SZ_BDF = (size_t)BB * 256 * 4;

static constexpr size_t O_XG_H  = 0;
static constexpr size_t O_XG_L  = O_XG_H  + SZ_XG;
static constexpr size_t O_XE_H  = O_XG_L  + SZ_XG;
static constexpr size_t O_XE_L  = O_XE_H  + SZ_XG;
static constexpr size_t O_XQS_H = O_XE_L  + SZ_XG;
static constexpr size_t O_XQS_L = O_XQS_H + SZ_XS;
static constexpr size_t O_XRS_H = O_XQS_L + SZ_XS;
static constexpr size_t O_XRS_L = O_XRS_H + SZ_XS;
static constexpr size_t O_XPL_H = O_XRS_L + SZ_XS;
static constexpr size_t O_XPL_L = O_XPL_H + SZ_XS;
static constexpr size_t O_Q0_H  = O_XPL_L + SZ_XS;
static constexpr size_t O_Q0_L  = O_Q0_H  + SZ_Q0;
static constexpr size_t O_GH_H  = O_Q0_L  + SZ_Q0;
static constexpr size_t O_GH_L  = O_GH_H  + SZ_BD;
static constexpr size_t O_E0_H  = O_GH_L  + SZ_BD;
static constexpr size_t O_E0_L  = O_E0_H  + SZ_BD;
static constexpr size_t O_QS_H  = O_E0_L  + SZ_BD;
static constexpr size_t O_QS_L  = O_QS_H  + SZ_BD;
static constexpr size_t O_RS_H  = O_QS_L  + SZ_BD;
static constexpr size_t O_RS_L  = O_RS_H  + SZ_BD;
static constexpr size_t O_QSF   = O_RS_L  + SZ_BD;
static constexpr size_t O_RSF   = O_QSF   + SZ_BDF;
static constexpr size_t SZ_W768 = (size_t)768 * 768 * 2;
static constexpr size_t SZ_W512 = (size_t)768 * 512 * 2;
static constexpr size_t SZ_W256 = (size_t)768 * 256 * 2;
static constexpr size_t O_WGIH_H = O_RSF + SZ_BDF;
static constexpr size_t O_WGIH_L = O_WGIH_H + SZ_W768;
static constexpr size_t O_WGHH_H = O_WGIH_L + SZ_W768;
static constexpr size_t O_WGHH_L = O_WGHH_H + SZ_W256;
static constexpr size_t O_WPIH_H = O_WGHH_L + SZ_W256;
static constexpr size_t O_WPIH_L = O_WPIH_H + SZ_W512;
static constexpr size_t O_WPHH_H = O_WPIH_L + SZ_W512;
static constexpr size_t O_WPHH_L = O_WPHH_H + SZ_W256;
static constexpr size_t O_WLIH_H = O_WPHH_L + SZ_W256;
static constexpr size_t O_WLIH_L = O_WLIH_H + SZ_W512;
static constexpr size_t O_WLHH_H = O_WLIH_L + SZ_W512;
static constexpr size_t O_WLHH_L = O_WLHH_H + SZ_W256;
static constexpr size_t O_WRIH_H = O_WLHH_L + SZ_W256;
static constexpr size_t O_WRIH_L = O_WRIH_H + SZ_W512;
static constexpr size_t O_WRHH_H = O_WRIH_L + SZ_W512;
static constexpr size_t O_WRHH_L = O_WRHH_H + SZ_W256;
static constexpr size_t O_WEIH_H = O_WRHH_L + SZ_W256;
static constexpr size_t O_WEIH_L = O_WEIH_H + SZ_W768;
static constexpr size_t O_WEHH_H = O_WEIH_L + SZ_W768;
static constexpr size_t O_WEHH_L = O_WEHH_H + SZ_W256;
static constexpr size_t O_SELROW = O_WEHH_L + SZ_W256;
static constexpr size_t O_QMIDX  = O_SELROW + BB * 4;
static constexpr size_t POOL_SZ  = O_QMIDX + BB * 4;

__device__ __align__(1024) unsigned char g_pool[POOL_SZ];

// ================= helpers =================
__device__ __forceinline__ void bsplit(float x, __nv_bfloat16* hp, __nv_bfloat16* lp, size_t i) {
    __nv_bfloat16 h = __float2bfloat16(x);
    hp[i] = h;
    lp[i] = __float2bfloat16(x - __bfloat162float(h));
}

// ================= conv_all: vectorized x4 =================
struct ConvSeg { const float* src; __nv_bfloat16* hi; __nv_bfloat16* lo; int nblk; };
struct ConvTable { ConvSeg s[13]; };

__global__ void conv_all_kernel(ConvTable t) {
    int blk = blockIdx.x;
    #pragma unroll 1
    for (int i = 0; i < 13; i++) {
        int nb = t.s[i].nblk;
        if (blk < nb) {
            int idx = blk * 1024 + threadIdx.x * 4;
            float4 v = *(const float4*)(t.s[i].src + idx);
            __nv_bfloat16 h0 = __float2bfloat16(v.x);
            __nv_bfloat16 h1 = __float2bfloat16(v.y);
            __nv_bfloat16 h2 = __float2bfloat16(v.z);
            __nv_bfloat16 h3 = __float2bfloat16(v.w);
            __nv_bfloat16 l0 = __float2bfloat16(v.x - __bfloat162float(h0));
            __nv_bfloat16 l1 = __float2bfloat16(v.y - __bfloat162float(h1));
            __nv_bfloat16 l2 = __float2bfloat16(v.z - __bfloat162float(h2));
            __nv_bfloat16 l3 = __float2bfloat16(v.w - __bfloat162float(h3));
            __nv_bfloat162 hv0, hv1, lv0, lv1;
            hv0.x = h0; hv0.y = h1; hv1.x = h2; hv1.y = h3;
            lv0.x = l0; lv0.y = l1; lv1.x = l2; lv1.y = l3;
            *(__nv_bfloat162*)(t.s[i].hi + idx)     = hv0;
            *(__nv_bfloat162*)(t.s[i].hi + idx + 2) = hv1;
            *(__nv_bfloat162*)(t.s[i].lo + idx)     = lv0;
            *(__nv_bfloat162*)(t.s[i].lo + idx + 2) = lv1;
            return;
        }
        blk -= nb;
    }
}

// ================= prep =================
__global__ void prep_kernel(const float* __restrict__ U, const float* __restrict__ qmask,
                            const float* __restrict__ q0, const float* __restrict__ r0,
                            float* __restrict__ qsf, float* __restrict__ rsf,
                            __nv_bfloat16* qsh, __nv_bfloat16* qsl,
                            __nv_bfloat16* rsh, __nv_bfloat16* rsl,
                            __nv_bfloat16* xgh, __nv_bfloat16* xgl,
                            __nv_bfloat16* xqsh, __nv_bfloat16* xqsl,
                            __nv_bfloat16* xrsh, __nv_bfloat16* xrsl,
                            __nv_bfloat16* xplh, __nv_bfloat16* xpll,
                            __nv_bfloat16* xeh,  __nv_bfloat16* xel,
                            int* __restrict__ selrow, int* __restrict__ qmidx) {
    int i = blockIdx.x * 256 + threadIdx.x;
    int b = i >> 8, d = i & 255;
    int qm = (qmask[b * 2 + 1] > qmask[b * 2]) ? 1 : 0;
    if (d == 0) { qmidx[b] = qm; selrow[b] = b * 2 + qm; }
    float q = q0[(size_t)(b * 2 + qm) * DD + d];
    float r = r0[(size_t)(b * 2 + qm) * DD + d];
    float u = U[i];
    qsf[i] = q; rsf[i] = r;
    bsplit(q, qsh, qsl, i);
    bsplit(r, rsh, rsl, i);
    size_t o = (size_t)b * 768 + d;
    bsplit(q, xgh, xgl, o);
    bsplit(r, xgh, xgl, o + 256);
    bsplit(u, xgh, xgl, o + 512);
    size_t o2 = (size_t)b * 512 + 256 + d;
    bsplit(u, xqsh, xqsl, o2);
    bsplit(u, xrsh, xrsl, o2);
    bsplit(u, xplh, xpll, o2);
    bsplit(u, xeh, xel, o);
}

// ================= attention =================
__global__ void att_kernel(const float* __restrict__ gh, const float* __restrict__ attw,
                           __nv_bfloat16* __restrict__ xrsh, __nv_bfloat16* __restrict__ xrsl,
                           float* __restrict__ alpha_out) {
    extern __shared__ float sh[];
    __shared__ float s_aw[DD];
    __shared__ float s_scale[TT];
    __shared__ float s_alpha[TT];
    int b = blockIdx.x, tid = threadIdx.x;
    s_aw[tid] = attw[tid];
    for (int t = 0; t < TT; t++)
        sh[t * DD + tid] = gh[((size_t)t * BB + b) * DD + tid];
    __syncthreads();
    int w = tid >> 5, lane = tid & 31;
    for (int t = w; t < TT; t += 8) {
        float s = 0.f;
        #pragma unroll
        for (int i = 0; i < 8; i++) s += sh[t * DD + lane + i * 32] * s_aw[lane + i * 32];
        #pragma unroll
        for (int o = 16; o > 0; o >>= 1) s += __shfl_down_sync(0xffffffffu, s, o);
        if (lane == 0) s_scale[t] = s;
    }
    __syncthreads();
    if (w == 0) {
        float v0 = s_scale[lane], v1 = s_scale[lane + 32];
        float m = fmaxf(v0, v1);
        #pragma unroll
        for (int o = 16; o > 0; o >>= 1) m = fmaxf(m, __shfl_xor_sync(0xffffffffu, m, o));
        float e0 = expf(v0 - m), e1 = expf(v1 - m);
        float s = e0 + e1;
        #pragma unroll
        for (int o = 16; o > 0; o >>= 1) s += __shfl_xor_sync(0xffffffffu, s, o);
        float inv = 1.f / s;
        s_alpha[lane] = e0 * inv;
        s_alpha[lane + 32] = e1 * inv;
        alpha_out[(size_t)b * TT + lane] = e0 * inv;
        alpha_out[(size_t)b * TT + lane + 32] = e1 * inv;
    }
    __syncthreads();
    float acc = 0.f;
    for (int t = 0; t < TT; t++) acc += s_alpha[t] * sh[t * DD + tid];
    bsplit(acc, xrsh, xrsl, (size_t)b * 512 + tid);
}

// ================= fused GRU via mma.sync — m32n16 warp tile =================
// Block tile: 64 rows x 64 out-cols; 8 warps = 2(m) x 4(n); warp tile 32x16.
// Smem stage: A-hi(5120) A-lo(5120) + W[6 tiles x 64rows x 80B = 5120 each] = 40960 B.
// Double buffer = 81920 B. acc: 4 gates x 16 f32 = 64 regs, all static indices.
// Single barrier per chunk: wait_group 0 -> BARRIER -> prefetch -> consume.
#define ATILE 5120
#define WREG  10240
#define WTILE 5120
#define STAGE_SB 40960
#define GRU_SMEM (2 * STAGE_SB)

#define GATE2(ACCP, AF, BR) do { \
    mma16816((ACCP),     (AF), (BR)[0], (BR)[1]); \
    mma16816((ACCP) + 4, (AF), (BR)[2], (BR)[3]); \
} while (0)

__global__ __launch_bounds__(256, 2) void gru_mma_kernel(
    const __nv_bfloat16* __restrict__ Xhi, const __nv_bfloat16* __restrict__ Xlo,
    int K, int xshift,
    const __nv_bfloat16* __restrict__ Hhi, const __nv_bfloat16* __restrict__ Hlo,
    const float* __restrict__ Hf,
    const __nv_bfloat16* __restrict__ Wih_hi, const __nv_bfloat16* __restrict__ Wih_lo,
    const __nv_bfloat16* __restrict__ Whh_hi, const __nv_bfloat16* __restrict__ Whh_lo,
    const float* __restrict__ bih, const float* __restrict__ bhh,
    float* __restrict__ Out, const int* __restrict__ out_rows,
    const int* __restrict__ selrow, int zero_other,
    __nv_bfloat16* __restrict__ x1h, __nv_bfloat16* __restrict__ x1l,
    int x1_stride, int x1_off, int x1_sel,
    __nv_bfloat16* __restrict__ x2h, __nv_bfloat16* __restrict__ x2l,
    int x2_stride, int x2_off)
{
    extern __shared__ __align__(16) char dsm[];
    const uint32_t smb = smem_u32(dsm);

    const int tid = threadIdx.x;
    const int wid = tid >> 5, lane = tid & 31;
    const int warp_m = wid & 1, warp_n = wid >> 1;      // 2 m-warps x 4 n-warps
    const int row0 = blockIdx.x * 64, c0 = blockIdx.y * 64;

    const int nch0 = K / 32;
    const int ntot = nch0 + 8;

    float a0[16] = {}, a1[16] = {}, a2[16] = {}, a3[16] = {};

    // ---- loader setup: 8 vectors/thread/chunk (2 A + 6 W) ----
    const int lr = tid >> 2, lcv = tid & 3;
    const uint32_t sA = (uint32_t)lr * 80 + lcv * 16;
    uint32_t sW[6];
    int wgi[6], whl[6], wri[6], wci[6];
    #pragma unroll
    for (int j = 0; j < 6; j++) {
        int v = tid + 256 * j;           // 0..1535
        int rrow = v >> 2, c = v & 3;    // region row 0..383
        int tile = rrow >> 6;            // 0..5
        sW[j] = WREG + (uint32_t)tile * WTILE + (uint32_t)(rrow & 63) * 80 + c * 16;
        wgi[j] = tile >> 1; whl[j] = tile & 1; wri[j] = rrow & 63; wci[j] = c;
    }
    const __nv_bfloat16* pa  = Xhi + (size_t)((row0 + lr) >> xshift) * K + lcv * 8;
    const __nv_bfloat16* pal = Xlo + (size_t)((row0 + lr) >> xshift) * K + lcv * 8;
    const __nv_bfloat16* pw[6];
    #pragma unroll
    for (int j = 0; j < 6; j++)
        pw[j] = (whl[j] ? Wih_lo : Wih_hi)
              + (size_t)(wgi[j] * 256 + c0 + wri[j]) * K + wci[j] * 8;

    // ---- ldsm lane offsets (relative to stage base) ----
    const uint32_t AOFF = ((uint32_t)(warp_m * 32 + (lane & 7) + ((lane >> 3) & 1) * 8)) * 80
                        + (uint32_t)(lane >> 4) * 16;
    const uint32_t BOFF = WREG
                        + ((uint32_t)(warp_n * 16 + (lane & 7) + (lane >> 4) * 8)) * 80
                        + (uint32_t)((lane >> 3) & 1) * 16;

    #define PREF(SOFF) do { \
        cp16(smb + (SOFF) + sA,         pa); \
        cp16(smb + (SOFF) + sA + ATILE, pal); \
        cp16(smb + (SOFF) + sW[0], pw[0]); \
        cp16(smb + (SOFF) + sW[1], pw[1]); \
        cp16(smb + (SOFF) + sW[2], pw[2]); \
        cp16(smb + (SOFF) + sW[3], pw[3]); \
        cp16(smb + (SOFF) + sW[4], pw[4]); \
        cp16(smb + (SOFF) + sW[5], pw[5]); \
        pa += 32; pal += 32; \
        pw[0] += 32; pw[1] += 32; pw[2] += 32; \
        pw[3] += 32; pw[4] += 32; pw[5] += 32; \
    } while (0)

    PREF(0);
    asm volatile("cp.async.commit_group;");

    #pragma unroll 1
    for (int i = 0; i < ntot; i++) {
        asm volatile("cp.async.wait_group 0;");
        __syncthreads();

        if (i + 1 < ntot) {
            if (i + 1 == nch0) {
                pa  = Hhi + (size_t)(row0 + lr) * 256 + lcv * 8;
                pal = Hlo + (size_t)(row0 + lr) * 256 + lcv * 8;
                #pragma unroll
                for (int j = 0; j < 6; j++)
                    pw[j] = (whl[j] ? Whh_lo : Whh_hi)
                          + (size_t)(wgi[j] * 256 + c0 + wri[j]) * 256 + wci[j] * 8;
            }
            PREF(((i + 1) & 1) ? STAGE_SB : 0u);
            asm volatile("cp.async.commit_group;");
        }

        const uint32_t base = smb + ((i & 1) ? STAGE_SB : 0u);
        #pragma unroll
        for (int s = 0; s < 2; s++) {
            const uint32_t ka = (uint32_t)s * 32;
            uint32_t ah0[4], ah1[4], al0[4], al1[4], bh[4], bl[4];
            ldsm4(ah0, base + AOFF + ka);
            ldsm4(ah1, base + AOFF + 1280 + ka);          // +16 rows
            ldsm4(al0, base + AOFF + ATILE + ka);
            ldsm4(al1, base + AOFF + ATILE + 1280 + ka);
            // gate 0 -> a0
            ldsm4(bh, base + BOFF + ka);
            ldsm4(bl, base + BOFF + WTILE + ka);
            GATE2(a0,     ah0, bh); GATE2(a0 + 8, ah1, bh);
            GATE2(a0,     ah0, bl); GATE2(a0 + 8, ah1, bl);
            GATE2(a0,     al0, bh); GATE2(a0 + 8, al1, bh);
            // gate 1 -> a1
            ldsm4(bh, base + BOFF + 2 * WTILE + ka);
            ldsm4(bl, base + BOFF + 3 * WTILE + ka);
            GATE2(a1,     ah0, bh); GATE2(a1 + 8, ah1, bh);
            GATE2(a1,     ah0, bl); GATE2(a1 + 8, ah1, bl);
            GATE2(a1,     al0, bh); GATE2(a1 + 8, al1, bh);
            // gate 2 -> a2 (phase 0) or a3 (phase 1)
            ldsm4(bh, base + BOFF + 4 * WTILE + ka);
            ldsm4(bl, base + BOFF + 5 * WTILE + ka);
            if (i < nch0) {
                GATE2(a2,     ah0, bh); GATE2(a2 + 8, ah1, bh);
                GATE2(a2,     ah0, bl); GATE2(a2 + 8, ah1, bl);
                GATE2(a2,     al0, bh); GATE2(a2 + 8, al1, bh);
            } else {
                GATE2(a3,     ah0, bh); GATE2(a3 + 8, ah1, bh);
                GATE2(a3,     ah0, bl); GATE2(a3 + 8, ah1, bl);
                GATE2(a3,     al0, bh); GATE2(a3 + 8, al1, bh);
            }
        }
    }
    #undef PREF

    // ---- epilogue ----
    #pragma unroll
    for (int msub = 0; msub < 2; msub++) {
        const int mrowb = row0 + warp_m * 32 + msub * 16 + (lane >> 2);
        #pragma unroll
        for (int half = 0; half < 2; half++) {
            int m = mrowb + half * 8;
            int orow = out_rows ? out_rows[m] : m;
            const float* hrow = Hf + (size_t)m * 256;
            float* op = Out + (size_t)orow * 256;
            float* oo = zero_other ? (Out + (size_t)(orow ^ 1) * 256) : nullptr;
            int x1b = x1_sel ? (m >> 1) : m;
            bool x1ok = x1h && (!x1_sel || (selrow[x1b] == m));
            #pragma unroll
            for (int nt = 0; nt < 2; nt++) {
                #pragma unroll
                for (int e = 0; e < 2; e++) {
                    int col = c0 + warp_n * 16 + (lane & 3) * 2 + nt * 8 + e;
                    int d = msub * 8 + nt * 4 + half * 2 + e;
                    float ar = a0[d] + bih[col] + bhh[col];
                    float az = a1[d] + bih[256 + col] + bhh[256 + col];
                    float r = 1.f / (1.f + expf(-ar));
                    float z = 1.f / (1.f + expf(-az));
                    float n = tanhf(a2[d] + bih[512 + col] + r * (a3[d] + bhh[512 + col]));
                    float v = (1.f - z) * n + z * hrow[col];
                    op[col] = v;
                    if (oo) oo[col] = 0.f;
                    if (x1ok) bsplit(v, x1h, x1l, (size_t)x1b * x1_stride + x1_off + col);
                    if (x2h)  bsplit(v, x2h, x2l, (size_t)m * x2_stride + x2_off + col);
                }
            }
        }
    }
}

// ================= launch =================
extern "C" void kernel_launch(void* const* d_in, const int* in_sizes, int n_in,
                              void* d_out, int out_size) {
    const float* U      = (const float*)d_in[0];
    const float* qmask  = (const float*)d_in[1];
    const float* g_hist = (const float*)d_in[2];
    const float* q0     = (const float*)d_in[3];
    const float* r0     = (const float*)d_in[4];
    const float* e0     = (const float*)d_in[5];
    const float* g_wih  = (const float*)d_in[6];
    const float* g_whh  = (const float*)d_in[7];
    const float* g_bih  = (const float*)d_in[8];
    const float* g_bhh  = (const float*)d_in[9];
    const float* p_wih  = (const float*)d_in[10];
    const float* p_whh  = (const float*)d_in[11];
    const float* p_bih  = (const float*)d_in[12];
    const float* p_bhh  = (const float*)d_in[13];
    const float* pl_wih = (const float*)d_in[14];
    const float* pl_whh = (const float*)d_in[15];
    const float* pl_bih = (const float*)d_in[16];
    const float* pl_bhh = (const float*)d_in[17];
    const float* r_wih  = (const float*)d_in[18];
    const float* r_whh  = (const float*)d_in[19];
    const float* r_bih  = (const float*)d_in[20];
    const float* r_bhh  = (const float*)d_in[21];
    const float* e_wih  = (const float*)d_in[22];
    const float* e_whh  = (const float*)d_in[23];
    const float* e_bih  = (const float*)d_in[24];
    const float* e_bhh  = (const float*)d_in[25];
    const float* att_w  = (const float*)d_in[26];

    float* out = (float*)d_out;
    float* o_g = out;
    float* o_q = out + 1048576;
    float* o_r = out + 3145728;
    float* o_e = out + 5242880;
    float* o_a = out + 6291456;

    void* poolv;
    cudaGetSymbolAddress(&poolv, g_pool);
    char* pool = (char*)poolv;
    #define BF(off) ((__nv_bfloat16*)(pool + (off)))
    #define FP(off) ((float*)(pool + (off)))
    int* selrow = (int*)(pool + O_SELROW);
    int* qmidx  = (int*)(pool + O_QMIDX);

    cudaFuncSetAttribute(att_kernel, cudaFuncAttributeMaxDynamicSharedMemorySize,
                         TT * DD * (int)sizeof(float));
    cudaFuncSetAttribute(gru_mma_kernel, cudaFuncAttributeMaxDynamicSharedMemorySize, GRU_SMEM);

    const float* ghl = g_hist + (size_t)63 * BB * DD;

    // 1) conversions
    ConvTable ct;
    int ti = 0, total_blk = 0;
    auto addseg = [&](const float* s, size_t oh, size_t ol, int n) {
        ct.s[ti].src = s; ct.s[ti].hi = BF(oh); ct.s[ti].lo = BF(ol);
        ct.s[ti].nblk = n / 1024; total_blk += n / 1024; ti++;
    };
    addseg(g_wih,  O_WGIH_H, O_WGIH_L, 768 * 768);
    addseg(g_whh,  O_WGHH_H, O_WGHH_L, 768 * 256);
    addseg(p_wih,  O_WPIH_H, O_WPIH_L, 768 * 512);
    addseg(p_whh,  O_WPHH_H, O_WPHH_L, 768 * 256);
    addseg(pl_wih, O_WLIH_H, O_WLIH_L, 768 * 512);
    addseg(pl_whh, O_WLHH_H, O_WLHH_L, 768 * 256);
    addseg(r_wih,  O_WRIH_H, O_WRIH_L, 768 * 512);
    addseg(r_whh,  O_WRHH_H, O_WRHH_L, 768 * 256);
    addseg(e_wih,  O_WEIH_H, O_WEIH_L, 768 * 768);
    addseg(e_whh,  O_WEHH_H, O_WEHH_L, 768 * 256);
    addseg(q0,     O_Q0_H,   O_Q0_L,   2 * BB * 256);
    addseg(ghl,    O_GH_H,   O_GH_L,   BB * 256);
    addseg(e0,     O_E0_H,   O_E0_L,   BB * 256);
    conv_all_kernel<<<total_blk, 256>>>(ct);

    // 2) prep
    prep_kernel<<<BB, 256>>>(U, qmask, q0, r0,
        FP(O_QSF), FP(O_RSF), BF(O_QS_H), BF(O_QS_L), BF(O_RS_H), BF(O_RS_L),
        BF(O_XG_H), BF(O_XG_L),
        BF(O_XQS_H), BF(O_XQS_L), BF(O_XRS_H), BF(O_XRS_L),
        BF(O_XPL_H), BF(O_XPL_L), BF(O_XE_H), BF(O_XE_L),
        selrow, qmidx);

    // 3) attention -> xrs first half + alpha
    att_kernel<<<BB, 256, TT * DD * sizeof(float)>>>(g_hist, att_w,
        BF(O_XRS_H), BF(O_XRS_L), o_a);

    // 4) g GRU: K=768; epilogue writes xqs[0:256] and xe[512:768]
    gru_mma_kernel<<<dim3(BB / 64, 4), 256, GRU_SMEM>>>(
        BF(O_XG_H), BF(O_XG_L), 768, 0,
        BF(O_GH_H), BF(O_GH_L), ghl,
        BF(O_WGIH_H), BF(O_WGIH_L), BF(O_WGHH_H), BF(O_WGHH_L),
        g_bih, g_bhh, o_g, nullptr,
        nullptr, 0,
        BF(O_XQS_H), BF(O_XQS_L), 512, 0, 0,
        BF(O_XE_H), BF(O_XE_L), 768, 512);

    // 5) qs GRU: 8192 rows; epilogue writes xpl[0:256] for selected rows
    gru_mma_kernel<<<dim3(2 * BB / 64, 4), 256, GRU_SMEM>>>(
        BF(O_XQS_H), BF(O_XQS_L), 512, 1,
        BF(O_Q0_H), BF(O_Q0_L), q0,
        BF(O_WPIH_H), BF(O_WPIH_L), BF(O_WPHH_H), BF(O_WPHH_L),
        p_bih, p_bhh, o_q, nullptr,
        selrow, 0,
        BF(O_XPL_H), BF(O_XPL_L), 512, 0, 1,
        nullptr, nullptr, 0, 0);

    // 6) rs GRU: selected rows, scatter + zero sibling row   [ncu slot 6]
    gru_mma_kernel<<<dim3(BB / 64, 4), 256, GRU_SMEM>>>(
        BF(O_XRS_H), BF(O_XRS_L), 512, 0,
        BF(O_RS_H), BF(O_RS_L), FP(O_RSF),
        BF(O_WRIH_H), BF(O_WRIH_L), BF(O_WRHH_H), BF(O_WRHH_L),
        r_bih, r_bhh, o_r, selrow,
        nullptr, 1,
        nullptr, nullptr, 0, 0, 0,
        nullptr, nullptr, 0, 0);

    // 7) ql GRU: selected rows, scatter into q_; epilogue writes xe[256:512]
    gru_mma_kernel<<<dim3(BB / 64, 4), 256, GRU_SMEM>>>(
        BF(O_XPL_H), BF(O_XPL_L), 512, 0,
        BF(O_QS_H), BF(O_QS_L), FP(O_QSF),
        BF(O_WLIH_H), BF(O_WLIH_L), BF(O_WLHH_H), BF(O_WLHH_L),
        pl_bih, pl_bhh, o_q, selrow,
        nullptr, 0,
        BF(O_XE_H), BF(O_XE_L), 768, 256, 0,
        nullptr, nullptr, 0, 0);

    // 8) e GRU: K=768
    gru_mma_kernel<<<dim3(BB / 64, 4), 256, GRU_SMEM>>>(
        BF(O_XE_H), BF(O_XE_L), 768, 0,
        BF(O_E0_H), BF(O_E0_L), e0,
        BF(O_WEIH_H), BF(O_WEIH_L), BF(O_WEHH_H), BF(O_WEHH_L),
        e_bih, e_bhh, o_e, nullptr,
        nullptr, 0,
        nullptr, nullptr, 0, 0, 0,
        nullptr, nullptr, 0, 0);
    #undef BF
    #undef FP
}